// round 1
// baseline (speedup 1.0000x reference)
#include <cuda_runtime.h>

#define NB 8
#define NS 512
#define ND 768
#define NH 256
#define NC 32

// ---- scratch (device globals; no runtime allocation) ----
__device__ float g_Hs[NB * NS * NH];                 // 4 MB
__device__ float g_He[NB * NS * NH];                 // 4 MB
__device__ float g_Ls[NB * NS * NC];                 // 0.5 MB
__device__ float g_Le[NB * NS * NC];                 // 0.5 MB  (includes +W_b)
__device__ float g_M[(size_t)NB * NS * NC * NH];     // 134 MB  [b][e][c][h]
__device__ float g_Ur[NC * NH * NH];                 // 8.4 MB  [(c*NH+h)][g]

// ---- U rearrange: Ur[(c*256+h)*256 + g] = U[h,c,g] ----
__global__ void rearrange_U_kernel(const float* __restrict__ U) {
    int idx = blockIdx.x * blockDim.x + threadIdx.x;   // exact grid: NC*NH*NH threads
    int g = idx & (NH - 1);
    int h = (idx >> 8) & (NH - 1);
    int c = idx >> 16;
    g_Ur[idx] = U[(size_t)h * (NC * NH) + c * NH + g];
}

// ---- Ls/Le: Ls[bs,c] = Hs[bs,:]·W_w[c,:256] ; Le[bs,c] = He[bs,:]·W_w[c,256:] + W_b[c] ----
__global__ void lin_terms_kernel(const float* __restrict__ W_w,
                                 const float* __restrict__ W_b) {
    int c  = threadIdx.x;                               // 0..31
    int bs = blockIdx.x * blockDim.y + threadIdx.y;     // 0..NB*NS-1
    const float* hs = &g_Hs[(size_t)bs * NH];
    const float* he = &g_He[(size_t)bs * NH];
    const float* ws = &W_w[(size_t)c * (2 * NH)];
    float accs = 0.f, acce = 0.f;
#pragma unroll 4
    for (int h = 0; h < NH; ++h) {
        accs = fmaf(hs[h], ws[h], accs);
        acce = fmaf(he[h], ws[NH + h], acce);
    }
    g_Ls[(size_t)bs * NC + c] = accs;
    g_Le[(size_t)bs * NC + c] = acce + W_b[c];
}

// ---- generic NT GEMM: C[m,n] = sum_k A[m*lda+k] * B[n*ldb+k]  (+ epilogue) ----
// 128x128 block tile, BK=16, 256 threads, 8x8 register tile.
// epi: 0 = none, 1 = +E0[n] (bias over n), 2 = +Ls[b,s,c] + Le[b,e,c]
__global__ void __launch_bounds__(256) gemm_nt_kernel(
    const float* __restrict__ A, const float* __restrict__ Bmat,
    float* __restrict__ C,
    int K, int lda, int ldb, int ldc,
    long sA, long sB, long sC,
    int epi, const float* __restrict__ E0, const float* __restrict__ E1)
{
    const int bz = blockIdx.z;
    A    += (long)bz * sA;
    Bmat += (long)bz * sB;
    C    += (long)bz * sC;

    __shared__ float As[16][132];
    __shared__ float Bs[16][132];

    const int tid = threadIdx.x;
    const int bm = blockIdx.y * 128;
    const int bn = blockIdx.x * 128;

    const int tm = (tid >> 4) * 8;      // 0..120
    const int tn = (tid & 15) * 8;      // 0..120

    const int lr = tid >> 2;            // 0..63
    const int lk = (tid & 3) * 4;       // 0,4,8,12

    const float* Ap = A    + (long)(bm + lr) * lda + lk;
    const float* Bp = Bmat + (long)(bn + lr) * ldb + lk;

    float acc[8][8] = {};

    const int nIter = K >> 4;
    for (int it = 0; it < nIter; ++it) {
        float4 a0 = *reinterpret_cast<const float4*>(Ap);
        float4 a1 = *reinterpret_cast<const float4*>(Ap + (long)64 * lda);
        float4 b0 = *reinterpret_cast<const float4*>(Bp);
        float4 b1 = *reinterpret_cast<const float4*>(Bp + (long)64 * ldb);
        Ap += 16; Bp += 16;

        __syncthreads();
        As[lk + 0][lr] = a0.x; As[lk + 1][lr] = a0.y;
        As[lk + 2][lr] = a0.z; As[lk + 3][lr] = a0.w;
        As[lk + 0][lr + 64] = a1.x; As[lk + 1][lr + 64] = a1.y;
        As[lk + 2][lr + 64] = a1.z; As[lk + 3][lr + 64] = a1.w;
        Bs[lk + 0][lr] = b0.x; Bs[lk + 1][lr] = b0.y;
        Bs[lk + 2][lr] = b0.z; Bs[lk + 3][lr] = b0.w;
        Bs[lk + 0][lr + 64] = b1.x; Bs[lk + 1][lr + 64] = b1.y;
        Bs[lk + 2][lr + 64] = b1.z; Bs[lk + 3][lr + 64] = b1.w;
        __syncthreads();

#pragma unroll
        for (int k = 0; k < 16; ++k) {
            float4 aA = *reinterpret_cast<const float4*>(&As[k][tm]);
            float4 aB = *reinterpret_cast<const float4*>(&As[k][tm + 4]);
            float4 bA = *reinterpret_cast<const float4*>(&Bs[k][tn]);
            float4 bB = *reinterpret_cast<const float4*>(&Bs[k][tn + 4]);
            float ar[8] = {aA.x, aA.y, aA.z, aA.w, aB.x, aB.y, aB.z, aB.w};
            float br[8] = {bA.x, bA.y, bA.z, bA.w, bB.x, bB.y, bB.z, bB.w};
#pragma unroll
            for (int i = 0; i < 8; ++i)
#pragma unroll
                for (int j = 0; j < 8; ++j)
                    acc[i][j] = fmaf(ar[i], br[j], acc[i][j]);
        }
    }

    if (epi == 1) {
        float eb[8];
#pragma unroll
        for (int j = 0; j < 8; ++j) eb[j] = E0[bn + tn + j];
#pragma unroll
        for (int i = 0; i < 8; ++i)
#pragma unroll
            for (int j = 0; j < 8; ++j) acc[i][j] += eb[j];
    } else if (epi == 2) {
        // n = e*32 + c ; a thread's 8 columns share one e (tn is 8-aligned)
        int n0 = bn + tn;
        int e  = n0 >> 5;
        int c0 = n0 & 31;
        const float* le = E1 + ((long)bz * NS + e) * NC + c0;
        float lev[8];
#pragma unroll
        for (int j = 0; j < 8; ++j) lev[j] = le[j];
#pragma unroll
        for (int i = 0; i < 8; ++i) {
            const float* ls = E0 + ((long)bz * NS + bm + tm + i) * NC + c0;
#pragma unroll
            for (int j = 0; j < 8; ++j) acc[i][j] += ls[j] + lev[j];
        }
    }

#pragma unroll
    for (int i = 0; i < 8; ++i) {
        float* crow = C + (long)(bm + tm + i) * ldc + bn + tn;
        *reinterpret_cast<float4*>(crow) =
            make_float4(acc[i][0], acc[i][1], acc[i][2], acc[i][3]);
        *reinterpret_cast<float4*>(crow + 4) =
            make_float4(acc[i][4], acc[i][5], acc[i][6], acc[i][7]);
    }
}

extern "C" void kernel_launch(void* const* d_in, const int* in_sizes, int n_in,
                              void* d_out, int out_size) {
    const float* seq  = (const float*)d_in[0];  // (B,S,D)
    const float* U    = (const float*)d_in[1];  // (H,C,H)
    const float* W_w  = (const float*)d_in[2];  // (C,2H)
    const float* W_b  = (const float*)d_in[3];  // (C,)
    const float* Ws_w = (const float*)d_in[4];  // (H,D)
    const float* Ws_b = (const float*)d_in[5];  // (H,)
    const float* We_w = (const float*)d_in[6];  // (H,D)
    const float* We_b = (const float*)d_in[7];  // (H,)
    float* out = (float*)d_out;                 // (B,S,S,C)

    float *Hs, *He, *Ls, *Le, *M, *Ur;
    cudaGetSymbolAddress((void**)&Hs, g_Hs);
    cudaGetSymbolAddress((void**)&He, g_He);
    cudaGetSymbolAddress((void**)&Ls, g_Ls);
    cudaGetSymbolAddress((void**)&Le, g_Le);
    cudaGetSymbolAddress((void**)&M,  g_M);
    cudaGetSymbolAddress((void**)&Ur, g_Ur);

    dim3 blk(256);

    // U rearrange (independent)
    rearrange_U_kernel<<<(NC * NH * NH) / 256, 256>>>(U);

    // Hs = seq @ Ws_w^T + Ws_b   : M=4096, N=256, K=768
    gemm_nt_kernel<<<dim3(NH / 128, (NB * NS) / 128, 1), blk>>>(
        seq, Ws_w, Hs, ND, ND, ND, NH, 0, 0, 0, 1, Ws_b, nullptr);

    // He = seq @ We_w^T + We_b
    gemm_nt_kernel<<<dim3(NH / 128, (NB * NS) / 128, 1), blk>>>(
        seq, We_w, He, ND, ND, ND, NH, 0, 0, 0, 1, We_b, nullptr);

    // Ls / Le (+W_b)
    lin_terms_kernel<<<(NB * NS) / 8, dim3(32, 8)>>>(W_w, W_b);

    // M[b,e,(c,h)] = He_b @ Ur^T : per-b GEMM 512 x 8192 x 256
    gemm_nt_kernel<<<dim3((NC * NH) / 128, NS / 128, NB), blk>>>(
        He, Ur, M, NH, NH, NH, NC * NH,
        (long)NS * NH, 0, (long)NS * NC * NH, 0, nullptr, nullptr);

    // Out[b,s,(e,c)] = Hs_b @ M_b^T + Ls + Le : per-b GEMM 512 x 16384 x 256
    gemm_nt_kernel<<<dim3((NS * NC) / 128, NS / 128, NB), blk>>>(
        Hs, M, out, NH, NH, NH, NS * NC,
        (long)NS * NH, (long)NS * NC * NH, (long)NS * NS * NC,
        2, Ls, Le);
}

// round 3
// speedup vs baseline: 2.0267x; 2.0267x over previous
#include <cuda_runtime.h>
#include <cuda_bf16.h>
#include <cstdint>

#define NB 8
#define NS 512
#define ND 768
#define NH 256
#define NC 32

// ---------------- scratch (device globals) ----------------
__device__ __align__(16) __nv_bfloat16 g_Hs_hi[NB * NS * NH];
__device__ __align__(16) __nv_bfloat16 g_Hs_lo[NB * NS * NH];
__device__ __align__(16) __nv_bfloat16 g_He_hi[NB * NS * NH];
__device__ __align__(16) __nv_bfloat16 g_He_lo[NB * NS * NH];
__device__ float g_He[NB * NS * NH];
__device__ __align__(16) __nv_bfloat16 g_Ur_hi[NC * NH * NH];
__device__ __align__(16) __nv_bfloat16 g_Ur_lo[NC * NH * NH];
__device__ __align__(16) __nv_bfloat16 g_M_hi[(size_t)NB * NS * NC * NH];
__device__ __align__(16) __nv_bfloat16 g_M_lo[(size_t)NB * NS * NC * NH];
__device__ float g_Le[NB * NS * NC];
__device__ float g_Wsp[NC * NH];

// ---------------- helpers ----------------
__device__ __forceinline__ uint32_t smem_u32(const void* p) {
    uint32_t a;
    asm("{ .reg .u64 t; cvta.to.shared.u64 t, %1; cvt.u32.u64 %0, t; }" : "=r"(a) : "l"(p));
    return a;
}
__device__ __forceinline__ void cp16(uint32_t s, const void* g) {
    asm volatile("cp.async.cg.shared.global [%0], [%1], 16;" :: "r"(s), "l"(g));
}
#define CP_COMMIT() asm volatile("cp.async.commit_group;" ::: "memory")
#define CP_WAIT1()  asm volatile("cp.async.wait_group 1;" ::: "memory")
#define CP_WAIT0()  asm volatile("cp.async.wait_group 0;" ::: "memory")

__device__ __forceinline__ void ldsm4(uint32_t& r0, uint32_t& r1, uint32_t& r2, uint32_t& r3, uint32_t a) {
    asm volatile("ldmatrix.sync.aligned.m8n8.x4.shared.b16 {%0,%1,%2,%3}, [%4];"
                 : "=r"(r0), "=r"(r1), "=r"(r2), "=r"(r3) : "r"(a));
}
__device__ __forceinline__ void mma16816(float* c, const uint32_t* a, uint32_t b0, uint32_t b1) {
    asm volatile("mma.sync.aligned.m16n8k16.row.col.f32.bf16.bf16.f32 "
                 "{%0,%1,%2,%3}, {%4,%5,%6,%7}, {%8,%9}, {%0,%1,%2,%3};"
                 : "+f"(c[0]), "+f"(c[1]), "+f"(c[2]), "+f"(c[3])
                 : "r"(a[0]), "r"(a[1]), "r"(a[2]), "r"(a[3]), "r"(b0), "r"(b1));
}
__device__ __forceinline__ uint32_t sw128(uint32_t off) {
    return off ^ ((off >> 3) & 0x70);
}
__device__ __forceinline__ void split2(float v, __nv_bfloat16& h, __nv_bfloat16& l) {
    h = __float2bfloat16(v);
    l = __float2bfloat16(v - __bfloat162float(h));
}

// ---------------- small prep kernels ----------------
__global__ void rearrange_U_kernel(const float* __restrict__ U) {
    int idx = blockIdx.x * 256 + threadIdx.x;   // NC*NH*NH total
    int g = idx & 255, h = (idx >> 8) & 255, c = idx >> 16;
    float u = U[(size_t)h * (NC * NH) + c * NH + g];
    __nv_bfloat16 hi, lo;
    split2(u, hi, lo);
    g_Ur_hi[idx] = hi;
    g_Ur_lo[idx] = lo;
}

__global__ void wsp_kernel(const float* __restrict__ W_w) {
    int i = blockIdx.x * 256 + threadIdx.x;     // 8192
    g_Wsp[i] = W_w[(i >> 8) * 512 + (i & 255)];
}

// Le[row, c] = He[row,:] . W_w[c, 256:512] + W_b[c]
__global__ void __launch_bounds__(256) le_kernel(const float* __restrict__ W_w,
                                                 const float* __restrict__ W_b) {
    __shared__ float We[32][257];
    int tid = threadIdx.x;
    for (int i = tid; i < 32 * 256; i += 256) {
        int c = i >> 8, g = i & 255;
        We[c][g] = W_w[c * 512 + 256 + g];
    }
    __syncthreads();
    int c = tid & 31, r = tid >> 5;
    int row = blockIdx.x * 8 + r;
    const float* he = g_He + (size_t)row * NH;
    float acc = 0.f;
#pragma unroll 8
    for (int g = 0; g < 256; ++g) acc = fmaf(he[g], We[c][g], acc);
    g_Le[(size_t)row * NC + c] = acc + W_b[c];
}

// ---------------- projection GEMM (fp32 FFMA): C = A(4096x768) @ B(256x768)^T + bias ----------------
__global__ void __launch_bounds__(256) gemm_proj_kernel(
    const float* __restrict__ A, const float* __restrict__ Bmat,
    float* __restrict__ Cf, __nv_bfloat16* __restrict__ Chi, __nv_bfloat16* __restrict__ Clo,
    const float* __restrict__ bias)
{
    __shared__ float As[16][132];
    __shared__ float Bs[16][132];

    const int tid = threadIdx.x;
    const int bm = blockIdx.y * 128;
    const int bn = blockIdx.x * 128;
    const int tm = (tid >> 4) * 8;
    const int tn = (tid & 15) * 8;
    const int lr = tid >> 2;
    const int lk = (tid & 3) * 4;

    const float* Ap = A    + (size_t)(bm + lr) * ND + lk;
    const float* Bp = Bmat + (size_t)(bn + lr) * ND + lk;

    float acc[8][8] = {};
    for (int it = 0; it < ND / 16; ++it) {
        float4 a0 = *reinterpret_cast<const float4*>(Ap);
        float4 a1 = *reinterpret_cast<const float4*>(Ap + (size_t)64 * ND);
        float4 b0 = *reinterpret_cast<const float4*>(Bp);
        float4 b1 = *reinterpret_cast<const float4*>(Bp + (size_t)64 * ND);
        Ap += 16; Bp += 16;

        __syncthreads();
        As[lk + 0][lr] = a0.x; As[lk + 1][lr] = a0.y; As[lk + 2][lr] = a0.z; As[lk + 3][lr] = a0.w;
        As[lk + 0][lr + 64] = a1.x; As[lk + 1][lr + 64] = a1.y; As[lk + 2][lr + 64] = a1.z; As[lk + 3][lr + 64] = a1.w;
        Bs[lk + 0][lr] = b0.x; Bs[lk + 1][lr] = b0.y; Bs[lk + 2][lr] = b0.z; Bs[lk + 3][lr] = b0.w;
        Bs[lk + 0][lr + 64] = b1.x; Bs[lk + 1][lr + 64] = b1.y; Bs[lk + 2][lr + 64] = b1.z; Bs[lk + 3][lr + 64] = b1.w;
        __syncthreads();

#pragma unroll
        for (int k = 0; k < 16; ++k) {
            float4 aA = *reinterpret_cast<const float4*>(&As[k][tm]);
            float4 aB = *reinterpret_cast<const float4*>(&As[k][tm + 4]);
            float4 bA = *reinterpret_cast<const float4*>(&Bs[k][tn]);
            float4 bB = *reinterpret_cast<const float4*>(&Bs[k][tn + 4]);
            float ar[8] = {aA.x, aA.y, aA.z, aA.w, aB.x, aB.y, aB.z, aB.w};
            float br[8] = {bA.x, bA.y, bA.z, bA.w, bB.x, bB.y, bB.z, bB.w};
#pragma unroll
            for (int i = 0; i < 8; ++i)
#pragma unroll
                for (int j = 0; j < 8; ++j)
                    acc[i][j] = fmaf(ar[i], br[j], acc[i][j]);
        }
    }

    float eb[8];
#pragma unroll
    for (int j = 0; j < 8; ++j) eb[j] = bias[bn + tn + j];

#pragma unroll
    for (int i = 0; i < 8; ++i) {
        size_t roff = (size_t)(bm + tm + i) * NH + bn + tn;
        __align__(16) __nv_bfloat16 hv[8], lv[8];
#pragma unroll
        for (int j = 0; j < 8; ++j) {
            float v = acc[i][j] + eb[j];
            acc[i][j] = v;
            split2(v, hv[j], lv[j]);
        }
        if (Cf) {
            *reinterpret_cast<float4*>(Cf + roff)     = make_float4(acc[i][0], acc[i][1], acc[i][2], acc[i][3]);
            *reinterpret_cast<float4*>(Cf + roff + 4) = make_float4(acc[i][4], acc[i][5], acc[i][6], acc[i][7]);
        }
        *reinterpret_cast<uint4*>(Chi + roff) = *reinterpret_cast<uint4*>(hv);
        *reinterpret_cast<uint4*>(Clo + roff) = *reinterpret_cast<uint4*>(lv);
    }
}

// ---------------- HMMA split-bf16 NT GEMM ----------------
// C[m,n] = sum_k A[m,k]*B[n,k] over hi/lo split (3 segments), K=256 per segment.
// Tile 128x128, BK=64, 256 threads, 8 warps (2m x 4n), warp tile 64x32.
// mode 1: C = acc + Wsp[n]      -> bf16 hi/lo pair
// mode 2: C = acc + Le[b,n]     -> fp32
#define STAGE_BYTES 32768   // A 16KB + B 16KB
#define SMEM_MM (2 * STAGE_BYTES)

__global__ void __launch_bounds__(256) gemm_mma_kernel(
    const __nv_bfloat16* __restrict__ Ahi, const __nv_bfloat16* __restrict__ Alo,
    const __nv_bfloat16* __restrict__ Bhi, const __nv_bfloat16* __restrict__ Blo,
    long sA, long sB,
    int mode, const float* __restrict__ aux,
    __nv_bfloat16* __restrict__ Chi, __nv_bfloat16* __restrict__ Clo,
    float* __restrict__ Cf, int ldc, long sC)
{
    extern __shared__ char smem[];
    const uint32_t sb = smem_u32(smem);

    const int tid  = threadIdx.x;
    const int wid  = tid >> 5;
    const int lane = tid & 31;
    const int b    = blockIdx.z;
    const int bm   = blockIdx.y * 128;
    const int bn   = blockIdx.x * 128;

    const __nv_bfloat16* Aseg[3];
    const __nv_bfloat16* Bseg[3];
    Aseg[0] = Ahi + (size_t)b * sA;  Bseg[0] = Bhi + (size_t)b * sB;
    Aseg[1] = Alo + (size_t)b * sA;  Bseg[1] = Bseg[0];
    Aseg[2] = Aseg[0];               Bseg[2] = Blo + (size_t)b * sB;

    // fill addressing: per thread 4 A-rows + 4 B-rows, one 16B unit each
    const int fr = tid >> 3;            // 0..31 (+32 per i)
    const int fk = tid & 7;             // 16B unit within 128B row
    const uint32_t sdst = sw128((uint32_t)(fr * 128 + fk * 16));

    // ldmatrix addressing (per ks later): row within tile, col-half
    const int wm = (wid & 1) * 64;      // m-warp offset
    const int wn = (wid >> 1) * 32;     // n-warp offset
    const int lrow = lane & 15;
    const int lhalf = lane >> 4;

    float acc[4][4][4] = {};

    auto fill = [&](int c, int s) {
        const int seg = c >> 2;
        const int ko  = (c & 3) * 64;
        const __nv_bfloat16* Ag = Aseg[seg] + ko;
        const __nv_bfloat16* Bg = Bseg[seg] + ko;
        const uint32_t abase = sb + s * STAGE_BYTES;
        const uint32_t bbase = abase + 16384;
#pragma unroll
        for (int i = 0; i < 4; ++i) {
            int r = fr + i * 32;
            uint32_t d = sdst + sw128((uint32_t)(i * 32 * 128)) - sw128(0); // i*32 rows: swizzle row bits unaffected by +32*128? compute directly:
            d = sw128((uint32_t)(r * 128 + fk * 16));
            cp16(abase + d, Ag + (size_t)(bm + r) * 256 + fk * 8);
            cp16(bbase + d, Bg + (size_t)(bn + r) * 256 + fk * 8);
        }
        CP_COMMIT();
    };

    auto compute = [&](int s) {
        const uint32_t abase = sb + s * STAGE_BYTES;
        const uint32_t bbase = abase + 16384;
#pragma unroll
        for (int ks = 0; ks < 4; ++ks) {
            uint32_t af[4][4];
#pragma unroll
            for (int mt = 0; mt < 4; ++mt) {
                int row = wm + mt * 16 + lrow;
                uint32_t a = abase + sw128((uint32_t)(row * 128 + ks * 32 + lhalf * 16));
                ldsm4(af[mt][0], af[mt][1], af[mt][2], af[mt][3], a);
            }
            uint32_t bfm[2][4];
#pragma unroll
            for (int bp = 0; bp < 2; ++bp) {
                int row = wn + bp * 16 + lrow;
                uint32_t a = bbase + sw128((uint32_t)(row * 128 + ks * 32 + lhalf * 16));
                ldsm4(bfm[bp][0], bfm[bp][1], bfm[bp][2], bfm[bp][3], a);
            }
#pragma unroll
            for (int mt = 0; mt < 4; ++mt)
#pragma unroll
                for (int nt = 0; nt < 4; ++nt) {
                    int bp = nt >> 1, q = nt & 1;
                    mma16816(acc[mt][nt], af[mt], bfm[bp][q], bfm[bp][q + 2]);
                }
        }
    };

    fill(0, 0);
    for (int c = 0; c < 12; ++c) {
        const int s = c & 1;
        if (c + 1 < 12) {
            fill(c + 1, s ^ 1);
            CP_WAIT1();
        } else {
            CP_WAIT0();
        }
        __syncthreads();
        compute(s);
        __syncthreads();
    }

    // ---------------- epilogue ----------------
    const int rbase = bm + wm + (lane >> 2);
    const int cbase = bn + wn + (lane & 3) * 2;
    if (mode == 1) {
        const size_t cb = (size_t)b * sC;
#pragma unroll
        for (int mt = 0; mt < 4; ++mt)
#pragma unroll
            for (int nt = 0; nt < 4; ++nt) {
                int r0 = rbase + mt * 16;
                int cn = cbase + nt * 8;
                float w0 = aux[cn], w1 = aux[cn + 1];
#pragma unroll
                for (int h = 0; h < 2; ++h) {
                    int r = r0 + h * 8;
                    float v0 = acc[mt][nt][h * 2 + 0] + w0;
                    float v1 = acc[mt][nt][h * 2 + 1] + w1;
                    __nv_bfloat16 h0, l0, h1, l1;
                    split2(v0, h0, l0);
                    split2(v1, h1, l1);
                    __nv_bfloat162 th; th.x = h0; th.y = h1;
                    __nv_bfloat162 tl; tl.x = l0; tl.y = l1;
                    *reinterpret_cast<__nv_bfloat162*>(Chi + cb + (size_t)r * ldc + cn) = th;
                    *reinterpret_cast<__nv_bfloat162*>(Clo + cb + (size_t)r * ldc + cn) = tl;
                }
            }
    } else {
        const float* le = aux + (size_t)b * (NS * NC);
        float* Co = Cf + (size_t)b * sC;
#pragma unroll
        for (int mt = 0; mt < 4; ++mt)
#pragma unroll
            for (int nt = 0; nt < 4; ++nt) {
                int r0 = rbase + mt * 16;
                int cn = cbase + nt * 8;
                float e0 = le[cn], e1 = le[cn + 1];
#pragma unroll
                for (int h = 0; h < 2; ++h) {
                    int r = r0 + h * 8;
                    float2 v;
                    v.x = acc[mt][nt][h * 2 + 0] + e0;
                    v.y = acc[mt][nt][h * 2 + 1] + e1;
                    *reinterpret_cast<float2*>(Co + (size_t)r * ldc + cn) = v;
                }
            }
    }
}

// ---------------- launch ----------------
extern "C" void kernel_launch(void* const* d_in, const int* in_sizes, int n_in,
                              void* d_out, int out_size) {
    const float* seq  = (const float*)d_in[0];
    const float* U    = (const float*)d_in[1];
    const float* W_w  = (const float*)d_in[2];
    const float* W_b  = (const float*)d_in[3];
    const float* Ws_w = (const float*)d_in[4];
    const float* Ws_b = (const float*)d_in[5];
    const float* We_w = (const float*)d_in[6];
    const float* We_b = (const float*)d_in[7];
    float* out = (float*)d_out;

    __nv_bfloat16 *Hs_hi, *Hs_lo, *He_hi, *He_lo, *Ur_hi, *Ur_lo, *M_hi, *M_lo;
    float *HeF, *Le, *Wsp;
    cudaGetSymbolAddress((void**)&Hs_hi, g_Hs_hi);
    cudaGetSymbolAddress((void**)&Hs_lo, g_Hs_lo);
    cudaGetSymbolAddress((void**)&He_hi, g_He_hi);
    cudaGetSymbolAddress((void**)&He_lo, g_He_lo);
    cudaGetSymbolAddress((void**)&Ur_hi, g_Ur_hi);
    cudaGetSymbolAddress((void**)&Ur_lo, g_Ur_lo);
    cudaGetSymbolAddress((void**)&M_hi,  g_M_hi);
    cudaGetSymbolAddress((void**)&M_lo,  g_M_lo);
    cudaGetSymbolAddress((void**)&HeF,   g_He);
    cudaGetSymbolAddress((void**)&Le,    g_Le);
    cudaGetSymbolAddress((void**)&Wsp,   g_Wsp);

    cudaFuncSetAttribute(gemm_mma_kernel, cudaFuncAttributeMaxDynamicSharedMemorySize, SMEM_MM);

    rearrange_U_kernel<<<(NC * NH * NH) / 256, 256>>>(U);
    wsp_kernel<<<(NC * NH) / 256, 256>>>(W_w);

    gemm_proj_kernel<<<dim3(2, 32), 256>>>(seq, Ws_w, nullptr, Hs_hi, Hs_lo, Ws_b);
    gemm_proj_kernel<<<dim3(2, 32), 256>>>(seq, We_w, HeF,     He_hi, He_lo, We_b);

    le_kernel<<<(NB * NS) / 8, 256>>>(W_w, W_b);

    // GEMM1: M'[b, e, (c,h)] = He_b @ Ur^T + W_s  -> bf16 hi/lo   (M=512, N=8192, K=256)
    gemm_mma_kernel<<<dim3((NC * NH) / 128, NS / 128, NB), 256, SMEM_MM>>>(
        He_hi, He_lo, Ur_hi, Ur_lo,
        (long)NS * NH, 0L,
        1, Wsp, M_hi, M_lo, nullptr, NC * NH, (long)NS * NC * NH);

    // GEMM2: out[b, s, (e,c)] = Hs_b @ M'_b^T + Le -> fp32        (M=512, N=16384, K=256)
    gemm_mma_kernel<<<dim3((NS * NC) / 128, NS / 128, NB), 256, SMEM_MM>>>(
        Hs_hi, Hs_lo, M_hi, M_lo,
        (long)NS * NH, (long)NS * NC * NH,
        2, Le, nullptr, nullptr, out, NS * NC, (long)NS * NS * NC);
}

// round 6
// speedup vs baseline: 3.3348x; 1.6455x over previous
#include <cuda_runtime.h>
#include <cuda_fp16.h>
#include <cstdint>

#define NB 8
#define NS 512
#define ND 768
#define NH 256
#define NC 32

// ---------------- scratch (device globals) ----------------
__device__ __align__(16) __half g_seq_hi[NB * NS * ND];
__device__ __align__(16) __half g_seq_lo[NB * NS * ND];
__device__ __align__(16) __half g_Wcat_hi[2 * NH * ND];   // rows 0-255 Ws_w, 256-511 We_w
__device__ __align__(16) __half g_Wcat_lo[2 * NH * ND];
__device__ float g_bcat[2 * NH];
__device__ __align__(16) __half g_Hs_hi[NB * NS * NH];
__device__ __align__(16) __half g_Hs_lo[NB * NS * NH];
__device__ __align__(16) __half g_He_hi[NB * NS * NH];
__device__ __align__(16) __half g_He_lo[NB * NS * NH];
__device__ __align__(16) __half g_Ur_hi[NC * NH * NH];
__device__ __align__(16) __half g_Ur_lo[NC * NH * NH];
__device__ __align__(16) __half g_M[(size_t)NB * NS * NC * NH];   // single fp16
__device__ float g_Le[NB * NS * NC];
__device__ float g_Wsp[NC * NH];

// ---------------- helpers ----------------
__device__ __forceinline__ uint32_t smem_u32(const void* p) {
    uint32_t a;
    asm("{ .reg .u64 t; cvta.to.shared.u64 t, %1; cvt.u32.u64 %0, t; }" : "=r"(a) : "l"(p));
    return a;
}
__device__ __forceinline__ void cp16(uint32_t s, const void* g) {
    asm volatile("cp.async.cg.shared.global [%0], [%1], 16;" :: "r"(s), "l"(g));
}
#define CP_COMMIT() asm volatile("cp.async.commit_group;" ::: "memory")
#define CP_WAIT1()  asm volatile("cp.async.wait_group 1;" ::: "memory")
#define CP_WAIT0()  asm volatile("cp.async.wait_group 0;" ::: "memory")

__device__ __forceinline__ void ldsm4(uint32_t& r0, uint32_t& r1, uint32_t& r2, uint32_t& r3, uint32_t a) {
    asm volatile("ldmatrix.sync.aligned.m8n8.x4.shared.b16 {%0,%1,%2,%3}, [%4];"
                 : "=r"(r0), "=r"(r1), "=r"(r2), "=r"(r3) : "r"(a));
}
__device__ __forceinline__ void mma16816(float* c, const uint32_t* a, uint32_t b0, uint32_t b1) {
    asm volatile("mma.sync.aligned.m16n8k16.row.col.f32.f16.f16.f32 "
                 "{%0,%1,%2,%3}, {%4,%5,%6,%7}, {%8,%9}, {%0,%1,%2,%3};"
                 : "+f"(c[0]), "+f"(c[1]), "+f"(c[2]), "+f"(c[3])
                 : "r"(a[0]), "r"(a[1]), "r"(a[2]), "r"(a[3]), "r"(b0), "r"(b1));
}
__device__ __forceinline__ uint32_t sw128(uint32_t off) {
    return off ^ ((off >> 3) & 0x70);
}
__device__ __forceinline__ void split2h(float v, __half& h, __half& l) {
    h = __float2half_rn(v);
    l = __float2half_rn(v - __half2float(h));
}

// ---------------- prep kernels ----------------
__global__ void split_seq_kernel(const float* __restrict__ seq) {
    int i = blockIdx.x * 256 + threadIdx.x;      // over element pairs
    float2 v = reinterpret_cast<const float2*>(seq)[i];
    __half h0, l0, h1, l1;
    split2h(v.x, h0, l0);
    split2h(v.y, h1, l1);
    __half2 hh; hh.x = h0; hh.y = h1;
    __half2 ll; ll.x = l0; ll.y = l1;
    reinterpret_cast<__half2*>(g_seq_hi)[i] = hh;
    reinterpret_cast<__half2*>(g_seq_lo)[i] = ll;
}

__global__ void wcat_kernel(const float* __restrict__ Ws_w, const float* __restrict__ We_w,
                            const float* __restrict__ Ws_b, const float* __restrict__ We_b) {
    int i = blockIdx.x * 256 + threadIdx.x;      // 512*768
    int n = i / ND, d = i - n * ND;
    float v = (n < NH) ? Ws_w[n * ND + d] : We_w[(n - NH) * ND + d];
    __half h, l;
    split2h(v, h, l);
    g_Wcat_hi[i] = h;
    g_Wcat_lo[i] = l;
    if (i < 2 * NH) g_bcat[i] = (i < NH) ? Ws_b[i] : We_b[i - NH];
}

__global__ void rearrange_U_kernel(const float* __restrict__ U) {
    int idx = blockIdx.x * 256 + threadIdx.x;    // NC*NH*NH
    int g = idx & 255, h = (idx >> 8) & 255, c = idx >> 16;
    float u = U[(size_t)h * (NC * NH) + c * NH + g];
    __half hi, lo;
    split2h(u, hi, lo);
    g_Ur_hi[idx] = hi;
    g_Ur_lo[idx] = lo;
}

__global__ void wsp_kernel(const float* __restrict__ W_w) {
    int i = blockIdx.x * 256 + threadIdx.x;      // 8192
    g_Wsp[i] = W_w[(i >> 8) * 512 + (i & 255)];
}

// Le[row, c] = He[row,:] . W_w[c, 256:512] + W_b[c]   (He from fp16 hi/lo)
__global__ void __launch_bounds__(256) le_kernel(const float* __restrict__ W_w,
                                                 const float* __restrict__ W_b) {
    __shared__ float We[32][257];
    int tid = threadIdx.x;
    for (int i = tid; i < 32 * 256; i += 256) {
        int c = i >> 8, g = i & 255;
        We[c][g] = W_w[c * 512 + 256 + g];
    }
    __syncthreads();
    int c = tid & 31, r = tid >> 5;
    int row = blockIdx.x * 8 + r;
    const __half* hh = g_He_hi + (size_t)row * NH;
    const __half* hl = g_He_lo + (size_t)row * NH;
    float acc = 0.f;
#pragma unroll 8
    for (int g = 0; g < 256; ++g) {
        float he = __half2float(hh[g]) + __half2float(hl[g]);
        acc = fmaf(he, We[c][g], acc);
    }
    g_Le[(size_t)row * NC + c] = acc + W_b[c];
}

// ---------------- unified HMMA split-fp16 NT GEMM ----------------
// C[m,n] = sum over products of Ax[m,k]*Bx[n,k], K elems per row (lda=ldb=K).
// P=3: (A0,B0)+(A0,B1)+(A1,B0).  P=2: (A0,B0)+(A1,B0).
// Tile 128x128, BK=64, 256 threads, 8 warps (2m x 4n).
// MODE 0: proj  -> split output to (Oh,Ol) for n<256 else (Oh2,Ol2), +bcat[n]
// MODE 1: G1    -> single fp16 Oh, + aux[n]
// MODE 2: G2    -> fp32 Of, + aux[b*NS*NC + n]
template<int P, int MODE>
__global__ void __launch_bounds__(256) gemm_mma(
    const __half* __restrict__ A0, const __half* __restrict__ A1,
    const __half* __restrict__ B0, const __half* __restrict__ B1,
    long sA, long sB, int K,
    const float* __restrict__ aux,
    __half* __restrict__ Oh, __half* __restrict__ Ol,
    __half* __restrict__ Oh2, __half* __restrict__ Ol2,
    float* __restrict__ Of, int ldc, long sC)
{
    constexpr int NT = (P == 3) ? 4 : 3;              // tiles per stage
    constexpr uint32_t TILE_B = 16384;
    constexpr uint32_t STAGE = NT * TILE_B;

    extern __shared__ char smem[];
    const uint32_t sb = smem_u32(smem);

    const int tid  = threadIdx.x;
    const int wid  = tid >> 5;
    const int lane = tid & 31;
    const int b    = blockIdx.z;
    const int bm   = blockIdx.y * 128;
    const int bn   = blockIdx.x * 128;

    const __half* A0g = A0 + (size_t)b * sA;
    const __half* A1g = A1 + (size_t)b * sA;
    const __half* B0g = B0 + (size_t)b * sB;
    const __half* B1g = (P == 3) ? B1 + (size_t)b * sB : nullptr;

    const int fr = tid >> 3;            // 0..31
    const int fk = tid & 7;             // 16B unit in 128B row

    const int wm = (wid & 1) * 64;
    const int wn = (wid >> 1) * 32;
    const int lrow = lane & 15;
    const int lhalf = lane >> 4;

    float acc[4][4][4] = {};

    auto fill = [&](int c, int s) {
        const int ko = c * 64;
        const uint32_t base = sb + s * STAGE;
#pragma unroll
        for (int i = 0; i < 4; ++i) {
            int r = fr + i * 32;
            uint32_t d = sw128((uint32_t)(r * 128 + fk * 16));
            cp16(base + d,              A0g + (size_t)(bm + r) * K + ko + fk * 8);
            cp16(base + TILE_B + d,     A1g + (size_t)(bm + r) * K + ko + fk * 8);
            cp16(base + 2 * TILE_B + d, B0g + (size_t)(bn + r) * K + ko + fk * 8);
            if (P == 3)
                cp16(base + 3 * TILE_B + d, B1g + (size_t)(bn + r) * K + ko + fk * 8);
        }
        CP_COMMIT();
    };

    auto compute = [&](int s) {
        const uint32_t a0b = sb + s * STAGE;
        const uint32_t a1b = a0b + TILE_B;
        const uint32_t b0b = a0b + 2 * TILE_B;
        const uint32_t b1b = a0b + 3 * TILE_B;
#pragma unroll
        for (int ks = 0; ks < 4; ++ks) {
            const uint32_t coff = (uint32_t)(ks * 32 + lhalf * 16);
            uint32_t a0f[4][4];
#pragma unroll
            for (int mt = 0; mt < 4; ++mt) {
                int row = wm + mt * 16 + lrow;
                ldsm4(a0f[mt][0], a0f[mt][1], a0f[mt][2], a0f[mt][3],
                      a0b + sw128((uint32_t)(row * 128) + coff));
            }
            uint32_t b0f[2][4];
#pragma unroll
            for (int bp = 0; bp < 2; ++bp) {
                int row = wn + bp * 16 + lrow;
                ldsm4(b0f[bp][0], b0f[bp][1], b0f[bp][2], b0f[bp][3],
                      b0b + sw128((uint32_t)(row * 128) + coff));
            }
#pragma unroll
            for (int mt = 0; mt < 4; ++mt)
#pragma unroll
                for (int nt = 0; nt < 4; ++nt) {
                    int bp = nt >> 1, q = nt & 1;
                    mma16816(acc[mt][nt], a0f[mt], b0f[bp][q], b0f[bp][q + 2]);
                }
            if (P == 3) {
                uint32_t b1f[2][4];
#pragma unroll
                for (int bp = 0; bp < 2; ++bp) {
                    int row = wn + bp * 16 + lrow;
                    ldsm4(b1f[bp][0], b1f[bp][1], b1f[bp][2], b1f[bp][3],
                          b1b + sw128((uint32_t)(row * 128) + coff));
                }
#pragma unroll
                for (int mt = 0; mt < 4; ++mt)
#pragma unroll
                    for (int nt = 0; nt < 4; ++nt) {
                        int bp = nt >> 1, q = nt & 1;
                        mma16816(acc[mt][nt], a0f[mt], b1f[bp][q], b1f[bp][q + 2]);
                    }
            }
            uint32_t a1f[4][4];
#pragma unroll
            for (int mt = 0; mt < 4; ++mt) {
                int row = wm + mt * 16 + lrow;
                ldsm4(a1f[mt][0], a1f[mt][1], a1f[mt][2], a1f[mt][3],
                      a1b + sw128((uint32_t)(row * 128) + coff));
            }
#pragma unroll
            for (int mt = 0; mt < 4; ++mt)
#pragma unroll
                for (int nt = 0; nt < 4; ++nt) {
                    int bp = nt >> 1, q = nt & 1;
                    mma16816(acc[mt][nt], a1f[mt], b0f[bp][q], b0f[bp][q + 2]);
                }
        }
    };

    const int nchunks = K >> 6;
    fill(0, 0);
    for (int c = 0; c < nchunks; ++c) {
        const int s = c & 1;
        if (c + 1 < nchunks) {
            fill(c + 1, s ^ 1);
            CP_WAIT1();
        } else {
            CP_WAIT0();
        }
        __syncthreads();
        compute(s);
        __syncthreads();
    }

    // ---------------- epilogue ----------------
    const int rbase = bm + wm + (lane >> 2);
    const int cb0 = bn + wn + (lane & 3) * 2;
#pragma unroll
    for (int mt = 0; mt < 4; ++mt)
#pragma unroll
        for (int nt = 0; nt < 4; ++nt) {
            int r0 = rbase + mt * 16;
            int cn = cb0 + nt * 8;
#pragma unroll
            for (int h = 0; h < 2; ++h) {
                int r = r0 + h * 8;
                float v0 = acc[mt][nt][h * 2 + 0];
                float v1 = acc[mt][nt][h * 2 + 1];
                if (MODE == 0) {
                    v0 += aux[cn]; v1 += aux[cn + 1];
                    __half h0, l0, h1, l1;
                    split2h(v0, h0, l0);
                    split2h(v1, h1, l1);
                    __half2 th; th.x = h0; th.y = h1;
                    __half2 tl; tl.x = l0; tl.y = l1;
                    if (cn < NH) {
                        *reinterpret_cast<__half2*>(Oh + (size_t)r * NH + cn) = th;
                        *reinterpret_cast<__half2*>(Ol + (size_t)r * NH + cn) = tl;
                    } else {
                        *reinterpret_cast<__half2*>(Oh2 + (size_t)r * NH + cn - NH) = th;
                        *reinterpret_cast<__half2*>(Ol2 + (size_t)r * NH + cn - NH) = tl;
                    }
                } else if (MODE == 1) {
                    v0 += aux[cn]; v1 += aux[cn + 1];
                    __half2 t; t.x = __float2half_rn(v0); t.y = __float2half_rn(v1);
                    *reinterpret_cast<__half2*>(Oh + (size_t)b * sC + (size_t)r * ldc + cn) = t;
                } else {
                    const float* le = aux + (size_t)b * (NS * NC);
                    float2 t;
                    t.x = v0 + le[cn];
                    t.y = v1 + le[cn + 1];
                    *reinterpret_cast<float2*>(Of + (size_t)b * sC + (size_t)r * ldc + cn) = t;
                }
            }
        }
}

// ---------------- launch ----------------
extern "C" void kernel_launch(void* const* d_in, const int* in_sizes, int n_in,
                              void* d_out, int out_size) {
    const float* seq  = (const float*)d_in[0];
    const float* U    = (const float*)d_in[1];
    const float* W_w  = (const float*)d_in[2];
    const float* W_b  = (const float*)d_in[3];
    const float* Ws_w = (const float*)d_in[4];
    const float* Ws_b = (const float*)d_in[5];
    const float* We_w = (const float*)d_in[6];
    const float* We_b = (const float*)d_in[7];
    float* out = (float*)d_out;

    __half *seq_hi, *seq_lo, *Wc_hi, *Wc_lo, *Hs_hi, *Hs_lo, *He_hi, *He_lo, *Ur_hi, *Ur_lo, *M;
    float *bcat, *Le, *Wsp;
    cudaGetSymbolAddress((void**)&seq_hi, g_seq_hi);
    cudaGetSymbolAddress((void**)&seq_lo, g_seq_lo);
    cudaGetSymbolAddress((void**)&Wc_hi,  g_Wcat_hi);
    cudaGetSymbolAddress((void**)&Wc_lo,  g_Wcat_lo);
    cudaGetSymbolAddress((void**)&bcat,   g_bcat);
    cudaGetSymbolAddress((void**)&Hs_hi,  g_Hs_hi);
    cudaGetSymbolAddress((void**)&Hs_lo,  g_Hs_lo);
    cudaGetSymbolAddress((void**)&He_hi,  g_He_hi);
    cudaGetSymbolAddress((void**)&He_lo,  g_He_lo);
    cudaGetSymbolAddress((void**)&Ur_hi,  g_Ur_hi);
    cudaGetSymbolAddress((void**)&Ur_lo,  g_Ur_lo);
    cudaGetSymbolAddress((void**)&M,      g_M);
    cudaGetSymbolAddress((void**)&Le,     g_Le);
    cudaGetSymbolAddress((void**)&Wsp,    g_Wsp);

    const int SMEM_P3 = 2 * 4 * 16384;   // 128 KB
    const int SMEM_P2 = 2 * 3 * 16384;   // 96 KB
    cudaFuncSetAttribute(gemm_mma<3, 0>, cudaFuncAttributeMaxDynamicSharedMemorySize, SMEM_P3);
    cudaFuncSetAttribute(gemm_mma<3, 1>, cudaFuncAttributeMaxDynamicSharedMemorySize, SMEM_P3);
    cudaFuncSetAttribute(gemm_mma<2, 2>, cudaFuncAttributeMaxDynamicSharedMemorySize, SMEM_P2);

    // prep
    rearrange_U_kernel<<<(NC * NH * NH) / 256, 256>>>(U);
    wsp_kernel<<<(NC * NH) / 256, 256>>>(W_w);
    wcat_kernel<<<(2 * NH * ND) / 256, 256>>>(Ws_w, We_w, Ws_b, We_b);
    split_seq_kernel<<<(NB * NS * ND / 2) / 256, 256>>>(seq);

    // fused projections: [Hs | He] = seq @ Wcat^T + bcat   (M=4096, N=512, K=768)
    gemm_mma<3, 0><<<dim3(4, 32, 1), 256, SMEM_P3>>>(
        seq_hi, seq_lo, Wc_hi, Wc_lo, 0L, 0L, ND,
        bcat, Hs_hi, Hs_lo, He_hi, He_lo, nullptr, NH, 0L);

    le_kernel<<<(NB * NS) / 8, 256>>>(W_w, W_b);

    // GEMM1: M[b, e, (c,h)] = He_b @ Ur^T + W_s  -> fp16   (512 x 8192 x 256)
    gemm_mma<3, 1><<<dim3(64, 4, NB), 256, SMEM_P3>>>(
        He_hi, He_lo, Ur_hi, Ur_lo,
        (long)NS * NH, 0L, NH,
        Wsp, M, nullptr, nullptr, nullptr, nullptr, NC * NH, (long)NS * NC * NH);

    // GEMM2: out[b, s, (e,c)] = Hs_b @ M_b^T + Le -> fp32  (512 x 16384 x 256)
    gemm_mma<2, 2><<<dim3(128, 4, NB), 256, SMEM_P2>>>(
        Hs_hi, Hs_lo, M, nullptr,
        (long)NS * NH, (long)NS * NC * NH, NH,
        Le, nullptr, nullptr, nullptr, nullptr, out, NS * NC, (long)NS * NS * NC);
}

// round 8
// speedup vs baseline: 3.6548x; 1.0960x over previous
#include <cuda_runtime.h>
#include <cuda_fp16.h>
#include <cstdint>

#define NB 8
#define NS 512
#define ND 768
#define NH 256
#define NC 32

// ---------------- scratch (device globals) ----------------
__device__ __align__(16) __half g_seq_hi[NB * NS * ND];
__device__ __align__(16) __half g_seq_lo[NB * NS * ND];
__device__ __align__(16) __half g_Wcat_hi[2 * NH * ND];   // rows 0-255 Ws_w, 256-511 We_w
__device__ __align__(16) __half g_Wcat_lo[2 * NH * ND];
__device__ float g_bcat[2 * NH];
__device__ __align__(16) __half g_Hs_hi[NB * NS * NH];
__device__ __align__(16) __half g_Hs_lo[NB * NS * NH];
__device__ __align__(16) __half g_He_hi[NB * NS * NH];
__device__ __align__(16) __half g_He_lo[NB * NS * NH];
__device__ __align__(16) __half g_Ur_hi[NC * NH * NH];
__device__ __align__(16) __half g_M[(size_t)NB * NS * NC * NH];   // single fp16
__device__ float g_Le[NB * NS * NC];
__device__ float g_Wsp[NC * NH];

// ---------------- helpers ----------------
__device__ __forceinline__ uint32_t smem_u32(const void* p) {
    uint32_t a;
    asm("{ .reg .u64 t; cvta.to.shared.u64 t, %1; cvt.u32.u64 %0, t; }" : "=r"(a) : "l"(p));
    return a;
}
__device__ __forceinline__ void cp16(uint32_t s, const void* g) {
    asm volatile("cp.async.cg.shared.global [%0], [%1], 16;" :: "r"(s), "l"(g));
}
#define CP_COMMIT() asm volatile("cp.async.commit_group;" ::: "memory")
#define CP_WAIT1()  asm volatile("cp.async.wait_group 1;" ::: "memory")
#define CP_WAIT0()  asm volatile("cp.async.wait_group 0;" ::: "memory")

__device__ __forceinline__ void ldsm4(uint32_t& r0, uint32_t& r1, uint32_t& r2, uint32_t& r3, uint32_t a) {
    asm volatile("ldmatrix.sync.aligned.m8n8.x4.shared.b16 {%0,%1,%2,%3}, [%4];"
                 : "=r"(r0), "=r"(r1), "=r"(r2), "=r"(r3) : "r"(a));
}
__device__ __forceinline__ void mma16816(float* c, const uint32_t* a, uint32_t b0, uint32_t b1) {
    asm volatile("mma.sync.aligned.m16n8k16.row.col.f32.f16.f16.f32 "
                 "{%0,%1,%2,%3}, {%4,%5,%6,%7}, {%8,%9}, {%0,%1,%2,%3};"
                 : "+f"(c[0]), "+f"(c[1]), "+f"(c[2]), "+f"(c[3])
                 : "r"(a[0]), "r"(a[1]), "r"(a[2]), "r"(a[3]), "r"(b0), "r"(b1));
}
__device__ __forceinline__ uint32_t sw128(uint32_t off) {
    return off ^ ((off >> 3) & 0x70);
}
__device__ __forceinline__ void split2h(float v, __half& h, __half& l) {
    h = __float2half_rn(v);
    l = __float2half_rn(v - __half2float(h));
}

// ---------------- prep kernels ----------------
__global__ void split_seq_kernel(const float* __restrict__ seq) {
    int i = blockIdx.x * 256 + threadIdx.x;      // over element pairs
    float2 v = reinterpret_cast<const float2*>(seq)[i];
    __half h0, l0, h1, l1;
    split2h(v.x, h0, l0);
    split2h(v.y, h1, l1);
    __half2 hh; hh.x = h0; hh.y = h1;
    __half2 ll; ll.x = l0; ll.y = l1;
    reinterpret_cast<__half2*>(g_seq_hi)[i] = hh;
    reinterpret_cast<__half2*>(g_seq_lo)[i] = ll;
}

__global__ void wcat_kernel(const float* __restrict__ Ws_w, const float* __restrict__ We_w,
                            const float* __restrict__ Ws_b, const float* __restrict__ We_b) {
    int i = blockIdx.x * 256 + threadIdx.x;      // 512*768
    int n = i / ND, d = i - n * ND;
    float v = (n < NH) ? Ws_w[n * ND + d] : We_w[(n - NH) * ND + d];
    __half h, l;
    split2h(v, h, l);
    g_Wcat_hi[i] = h;
    g_Wcat_lo[i] = l;
    if (i < 2 * NH) g_bcat[i] = (i < NH) ? Ws_b[i] : We_b[i - NH];
}

__global__ void rearrange_U_kernel(const float* __restrict__ U) {
    int idx = blockIdx.x * 256 + threadIdx.x;    // NC*NH*NH
    int g = idx & 255, h = (idx >> 8) & 255, c = idx >> 16;
    float u = U[(size_t)h * (NC * NH) + c * NH + g];
    g_Ur_hi[idx] = __float2half_rn(u);
}

__global__ void wsp_kernel(const float* __restrict__ W_w) {
    int i = blockIdx.x * 256 + threadIdx.x;      // 8192
    g_Wsp[i] = W_w[(i >> 8) * 512 + (i & 255)];
}

// Le[row, c] = He[row,:] . W_w[c, 256:512] + W_b[c]   (He from fp16 hi/lo)
__global__ void __launch_bounds__(256) le_kernel(const float* __restrict__ W_w,
                                                 const float* __restrict__ W_b) {
    __shared__ float We[32][257];
    int tid = threadIdx.x;
    for (int i = tid; i < 32 * 256; i += 256) {
        int c = i >> 8, g = i & 255;
        We[c][g] = W_w[c * 512 + 256 + g];
    }
    __syncthreads();
    int c = tid & 31, r = tid >> 5;
    int row = blockIdx.x * 8 + r;
    const __half* hh = g_He_hi + (size_t)row * NH;
    const __half* hl = g_He_lo + (size_t)row * NH;
    float acc = 0.f;
#pragma unroll 8
    for (int g = 0; g < 256; ++g) {
        float he = __half2float(hh[g]) + __half2float(hl[g]);
        acc = fmaf(he, We[c][g], acc);
    }
    g_Le[(size_t)row * NC + c] = acc + W_b[c];
}

// ---------------- unified HMMA split-fp16 NT GEMM ----------------
// C[m,n] = sum over products of Ax[m,k]*Bx[n,k], K elems per row (lda=ldb=K).
// P=3: (A0,B0)+(A0,B1)+(A1,B0).  P=2: (A0,B0)+(A1,B0).
// Tile 128x128, BK=64, 256 threads, 8 warps (2m x 4n).
// MODE 0: proj  -> split output to (Oh,Ol) for n<256 else (Oh2,Ol2), +bcat[n]
// MODE 1: G1    -> single fp16 Oh, + aux[n]
// MODE 2: G2    -> fp32 Of, + aux[b*NS*NC + n]
template<int P, int MODE>
__global__ void __launch_bounds__(256) gemm_mma(
    const __half* __restrict__ A0, const __half* __restrict__ A1,
    const __half* __restrict__ B0, const __half* __restrict__ B1,
    long sA, long sB, int K,
    const float* __restrict__ aux,
    __half* __restrict__ Oh, __half* __restrict__ Ol,
    __half* __restrict__ Oh2, __half* __restrict__ Ol2,
    float* __restrict__ Of, int ldc, long sC)
{
    constexpr int NT = (P == 3) ? 4 : 3;              // tiles per stage
    constexpr uint32_t TILE_B = 16384;
    constexpr uint32_t STAGE = NT * TILE_B;

    extern __shared__ char smem[];
    const uint32_t sb = smem_u32(smem);

    const int tid  = threadIdx.x;
    const int wid  = tid >> 5;
    const int lane = tid & 31;
    const int b    = blockIdx.z;
    const int bm   = blockIdx.y * 128;
    const int bn   = blockIdx.x * 128;

    const __half* A0g = A0 + (size_t)b * sA;
    const __half* A1g = A1 + (size_t)b * sA;
    const __half* B0g = B0 + (size_t)b * sB;
    const __half* B1g = (P == 3) ? B1 + (size_t)b * sB : nullptr;

    const int fr = tid >> 3;            // 0..31
    const int fk = tid & 7;             // 16B unit in 128B row

    const int wm = (wid & 1) * 64;
    const int wn = (wid >> 1) * 32;
    const int lrow = lane & 15;
    const int lhalf = lane >> 4;

    float acc[4][4][4] = {};

    auto fill = [&](int c, int s) {
        const int ko = c * 64;
        const uint32_t base = sb + s * STAGE;
#pragma unroll
        for (int i = 0; i < 4; ++i) {
            int r = fr + i * 32;
            uint32_t d = sw128((uint32_t)(r * 128 + fk * 16));
            cp16(base + d,              A0g + (size_t)(bm + r) * K + ko + fk * 8);
            cp16(base + TILE_B + d,     A1g + (size_t)(bm + r) * K + ko + fk * 8);
            cp16(base + 2 * TILE_B + d, B0g + (size_t)(bn + r) * K + ko + fk * 8);
            if (P == 3)
                cp16(base + 3 * TILE_B + d, B1g + (size_t)(bn + r) * K + ko + fk * 8);
        }
        CP_COMMIT();
    };

    auto compute = [&](int s) {
        const uint32_t a0b = sb + s * STAGE;
        const uint32_t a1b = a0b + TILE_B;
        const uint32_t b0b = a0b + 2 * TILE_B;
        const uint32_t b1b = a0b + 3 * TILE_B;
#pragma unroll
        for (int ks = 0; ks < 4; ++ks) {
            const uint32_t coff = (uint32_t)(ks * 32 + lhalf * 16);
            uint32_t a0f[4][4];
#pragma unroll
            for (int mt = 0; mt < 4; ++mt) {
                int row = wm + mt * 16 + lrow;
                ldsm4(a0f[mt][0], a0f[mt][1], a0f[mt][2], a0f[mt][3],
                      a0b + sw128((uint32_t)(row * 128) + coff));
            }
            uint32_t b0f[2][4];
#pragma unroll
            for (int bp = 0; bp < 2; ++bp) {
                int row = wn + bp * 16 + lrow;
                ldsm4(b0f[bp][0], b0f[bp][1], b0f[bp][2], b0f[bp][3],
                      b0b + sw128((uint32_t)(row * 128) + coff));
            }
#pragma unroll
            for (int mt = 0; mt < 4; ++mt)
#pragma unroll
                for (int nt = 0; nt < 4; ++nt) {
                    int bp = nt >> 1, q = nt & 1;
                    mma16816(acc[mt][nt], a0f[mt], b0f[bp][q], b0f[bp][q + 2]);
                }
            if (P == 3) {
                uint32_t b1f[2][4];
#pragma unroll
                for (int bp = 0; bp < 2; ++bp) {
                    int row = wn + bp * 16 + lrow;
                    ldsm4(b1f[bp][0], b1f[bp][1], b1f[bp][2], b1f[bp][3],
                          b1b + sw128((uint32_t)(row * 128) + coff));
                }
#pragma unroll
                for (int mt = 0; mt < 4; ++mt)
#pragma unroll
                    for (int nt = 0; nt < 4; ++nt) {
                        int bp = nt >> 1, q = nt & 1;
                        mma16816(acc[mt][nt], a0f[mt], b1f[bp][q], b1f[bp][q + 2]);
                    }
            }
            uint32_t a1f[4][4];
#pragma unroll
            for (int mt = 0; mt < 4; ++mt) {
                int row = wm + mt * 16 + lrow;
                ldsm4(a1f[mt][0], a1f[mt][1], a1f[mt][2], a1f[mt][3],
                      a1b + sw128((uint32_t)(row * 128) + coff));
            }
#pragma unroll
            for (int mt = 0; mt < 4; ++mt)
#pragma unroll
                for (int nt = 0; nt < 4; ++nt) {
                    int bp = nt >> 1, q = nt & 1;
                    mma16816(acc[mt][nt], a1f[mt], b0f[bp][q], b0f[bp][q + 2]);
                }
        }
    };

    const int nchunks = K >> 6;
    fill(0, 0);
    for (int c = 0; c < nchunks; ++c) {
        const int s = c & 1;
        if (c + 1 < nchunks) {
            fill(c + 1, s ^ 1);
            CP_WAIT1();
        } else {
            CP_WAIT0();
        }
        __syncthreads();
        compute(s);
        __syncthreads();
    }

    // ---------------- epilogue ----------------
    const int rbase = bm + wm + (lane >> 2);
    const int cb0 = bn + wn + (lane & 3) * 2;
#pragma unroll
    for (int mt = 0; mt < 4; ++mt)
#pragma unroll
        for (int nt = 0; nt < 4; ++nt) {
            int r0 = rbase + mt * 16;
            int cn = cb0 + nt * 8;
#pragma unroll
            for (int h = 0; h < 2; ++h) {
                int r = r0 + h * 8;
                float v0 = acc[mt][nt][h * 2 + 0];
                float v1 = acc[mt][nt][h * 2 + 1];
                if (MODE == 0) {
                    v0 += aux[cn]; v1 += aux[cn + 1];
                    __half h0, l0, h1, l1;
                    split2h(v0, h0, l0);
                    split2h(v1, h1, l1);
                    __half2 th; th.x = h0; th.y = h1;
                    __half2 tl; tl.x = l0; tl.y = l1;
                    if (cn < NH) {
                        *reinterpret_cast<__half2*>(Oh + (size_t)r * NH + cn) = th;
                        *reinterpret_cast<__half2*>(Ol + (size_t)r * NH + cn) = tl;
                    } else {
                        *reinterpret_cast<__half2*>(Oh2 + (size_t)r * NH + cn - NH) = th;
                        *reinterpret_cast<__half2*>(Ol2 + (size_t)r * NH + cn - NH) = tl;
                    }
                } else if (MODE == 1) {
                    v0 += aux[cn]; v1 += aux[cn + 1];
                    __half2 t; t.x = __float2half_rn(v0); t.y = __float2half_rn(v1);
                    *reinterpret_cast<__half2*>(Oh + (size_t)b * sC + (size_t)r * ldc + cn) = t;
                } else {
                    const float* le = aux + (size_t)b * (NS * NC);
                    float2 t;
                    t.x = v0 + le[cn];
                    t.y = v1 + le[cn + 1];
                    *reinterpret_cast<float2*>(Of + (size_t)b * sC + (size_t)r * ldc + cn) = t;
                }
            }
        }
}

// ---------------- launch ----------------
extern "C" void kernel_launch(void* const* d_in, const int* in_sizes, int n_in,
                              void* d_out, int out_size) {
    const float* seq  = (const float*)d_in[0];
    const float* U    = (const float*)d_in[1];
    const float* W_w  = (const float*)d_in[2];
    const float* W_b  = (const float*)d_in[3];
    const float* Ws_w = (const float*)d_in[4];
    const float* Ws_b = (const float*)d_in[5];
    const float* We_w = (const float*)d_in[6];
    const float* We_b = (const float*)d_in[7];
    float* out = (float*)d_out;

    __half *seq_hi, *seq_lo, *Wc_hi, *Wc_lo, *Hs_hi, *Hs_lo, *He_hi, *He_lo, *Ur_hi, *M;
    float *bcat, *Le, *Wsp;
    cudaGetSymbolAddress((void**)&seq_hi, g_seq_hi);
    cudaGetSymbolAddress((void**)&seq_lo, g_seq_lo);
    cudaGetSymbolAddress((void**)&Wc_hi,  g_Wcat_hi);
    cudaGetSymbolAddress((void**)&Wc_lo,  g_Wcat_lo);
    cudaGetSymbolAddress((void**)&bcat,   g_bcat);
    cudaGetSymbolAddress((void**)&Hs_hi,  g_Hs_hi);
    cudaGetSymbolAddress((void**)&Hs_lo,  g_Hs_lo);
    cudaGetSymbolAddress((void**)&He_hi,  g_He_hi);
    cudaGetSymbolAddress((void**)&He_lo,  g_He_lo);
    cudaGetSymbolAddress((void**)&Ur_hi,  g_Ur_hi);
    cudaGetSymbolAddress((void**)&M,      g_M);
    cudaGetSymbolAddress((void**)&Le,     g_Le);
    cudaGetSymbolAddress((void**)&Wsp,    g_Wsp);

    const int SMEM_P3 = 2 * 4 * 16384;   // 128 KB
    const int SMEM_P2 = 2 * 3 * 16384;   // 96 KB
    cudaFuncSetAttribute(gemm_mma<3, 0>, cudaFuncAttributeMaxDynamicSharedMemorySize, SMEM_P3);
    cudaFuncSetAttribute(gemm_mma<2, 1>, cudaFuncAttributeMaxDynamicSharedMemorySize, SMEM_P2);
    cudaFuncSetAttribute(gemm_mma<2, 2>, cudaFuncAttributeMaxDynamicSharedMemorySize, SMEM_P2);

    // prep
    rearrange_U_kernel<<<(NC * NH * NH) / 256, 256>>>(U);
    wsp_kernel<<<(NC * NH) / 256, 256>>>(W_w);
    wcat_kernel<<<(2 * NH * ND) / 256, 256>>>(Ws_w, We_w, Ws_b, We_b);
    split_seq_kernel<<<(NB * NS * ND / 2) / 256, 256>>>(seq);

    // fused projections: [Hs | He] = seq @ Wcat^T + bcat   (M=4096, N=512, K=768)
    gemm_mma<3, 0><<<dim3(4, 32, 1), 256, SMEM_P3>>>(
        seq_hi, seq_lo, Wc_hi, Wc_lo, 0L, 0L, ND,
        bcat, Hs_hi, Hs_lo, He_hi, He_lo, nullptr, NH, 0L);

    le_kernel<<<(NB * NS) / 8, 256>>>(W_w, W_b);

    // GEMM1: M[b, e, (c,h)] = (He_hi+He_lo)_b @ Ur_hi^T + W_s -> fp16  (512 x 8192 x 256)
    gemm_mma<2, 1><<<dim3(64, 4, NB), 256, SMEM_P2>>>(
        He_hi, He_lo, Ur_hi, nullptr,
        (long)NS * NH, 0L, NH,
        Wsp, M, nullptr, nullptr, nullptr, nullptr, NC * NH, (long)NS * NC * NH);

    // GEMM2: out[b, s, (e,c)] = (Hs_hi+Hs_lo)_b @ M_b^T + Le -> fp32   (512 x 16384 x 256)
    gemm_mma<2, 2><<<dim3(128, 4, NB), 256, SMEM_P2>>>(
        Hs_hi, Hs_lo, M, nullptr,
        (long)NS * NH, (long)NS * NC * NH, NH,
        Le, nullptr, nullptr, nullptr, nullptr, out, NS * NC, (long)NS * NS * NC);
}

// round 9
// speedup vs baseline: 4.9755x; 1.3614x over previous
#include <cuda_runtime.h>
#include <cuda_fp16.h>
#include <cstdint>

#define NB 8
#define NS 512
#define ND 768
#define NH 256
#define NC 32

// ---------------- scratch (device globals) ----------------
__device__ __align__(16) __half g_seq_hi[NB * NS * ND];
__device__ __align__(16) __half g_seq_lo[NB * NS * ND];
__device__ __align__(16) __half g_Wcat_hi[2 * NH * ND];   // rows 0-255 Ws_w, 256-511 We_w
__device__ __align__(16) __half g_Wcat_lo[2 * NH * ND];
__device__ float g_bcat[2 * NH];
__device__ __align__(16) __half g_Hs_hi[NB * NS * NH];
__device__ __align__(16) __half g_Hs_lo[NB * NS * NH];
__device__ __align__(16) __half g_He_hi[NB * NS * NH];
__device__ __align__(16) __half g_He_lo[NB * NS * NH];
__device__ __align__(16) __half g_Ur_hi[NC * NH * NH];
__device__ __align__(16) __half g_M[(size_t)NB * NS * NC * NH];   // single fp16
__device__ float g_Le[NB * NS * NC];
__device__ float g_Wsp[NC * NH];

// ---------------- helpers ----------------
__device__ __forceinline__ uint32_t smem_u32(const void* p) {
    uint32_t a;
    asm("{ .reg .u64 t; cvta.to.shared.u64 t, %1; cvt.u32.u64 %0, t; }" : "=r"(a) : "l"(p));
    return a;
}
__device__ __forceinline__ void cp16(uint32_t s, const void* g) {
    asm volatile("cp.async.cg.shared.global [%0], [%1], 16;" :: "r"(s), "l"(g));
}
#define CP_COMMIT() asm volatile("cp.async.commit_group;" ::: "memory")
#define CP_WAIT1()  asm volatile("cp.async.wait_group 1;" ::: "memory")
#define CP_WAIT0()  asm volatile("cp.async.wait_group 0;" ::: "memory")

__device__ __forceinline__ void ldsm4(uint32_t& r0, uint32_t& r1, uint32_t& r2, uint32_t& r3, uint32_t a) {
    asm volatile("ldmatrix.sync.aligned.m8n8.x4.shared.b16 {%0,%1,%2,%3}, [%4];"
                 : "=r"(r0), "=r"(r1), "=r"(r2), "=r"(r3) : "r"(a));
}
__device__ __forceinline__ void mma16816(float* c, const uint32_t* a, uint32_t b0, uint32_t b1) {
    asm volatile("mma.sync.aligned.m16n8k16.row.col.f32.f16.f16.f32 "
                 "{%0,%1,%2,%3}, {%4,%5,%6,%7}, {%8,%9}, {%0,%1,%2,%3};"
                 : "+f"(c[0]), "+f"(c[1]), "+f"(c[2]), "+f"(c[3])
                 : "r"(a[0]), "r"(a[1]), "r"(a[2]), "r"(a[3]), "r"(b0), "r"(b1));
}
__device__ __forceinline__ uint32_t sw128(uint32_t off) {
    return off ^ ((off >> 3) & 0x70);
}
__device__ __forceinline__ void split2h(float v, __half& h, __half& l) {
    h = __float2half_rn(v);
    l = __float2half_rn(v - __half2float(h));
}

// ---------------- prep kernels ----------------
__global__ void split_seq_kernel(const float* __restrict__ seq) {
    int i = blockIdx.x * 256 + threadIdx.x;      // over element pairs
    float2 v = reinterpret_cast<const float2*>(seq)[i];
    __half h0, l0, h1, l1;
    split2h(v.x, h0, l0);
    split2h(v.y, h1, l1);
    __half2 hh; hh.x = h0; hh.y = h1;
    __half2 ll; ll.x = l0; ll.y = l1;
    reinterpret_cast<__half2*>(g_seq_hi)[i] = hh;
    reinterpret_cast<__half2*>(g_seq_lo)[i] = ll;
}

__global__ void wcat_kernel(const float* __restrict__ Ws_w, const float* __restrict__ We_w,
                            const float* __restrict__ Ws_b, const float* __restrict__ We_b) {
    int i = blockIdx.x * 256 + threadIdx.x;      // 512*768
    int n = i / ND, d = i - n * ND;
    float v = (n < NH) ? Ws_w[n * ND + d] : We_w[(n - NH) * ND + d];
    __half h, l;
    split2h(v, h, l);
    g_Wcat_hi[i] = h;
    g_Wcat_lo[i] = l;
    if (i < 2 * NH) g_bcat[i] = (i < NH) ? Ws_b[i] : We_b[i - NH];
}

__global__ void rearrange_U_kernel(const float* __restrict__ U) {
    int idx = blockIdx.x * 256 + threadIdx.x;    // NC*NH*NH
    int g = idx & 255, h = (idx >> 8) & 255, c = idx >> 16;
    float u = U[(size_t)h * (NC * NH) + c * NH + g];
    g_Ur_hi[idx] = __float2half_rn(u);
}

__global__ void wsp_kernel(const float* __restrict__ W_w) {
    int i = blockIdx.x * 256 + threadIdx.x;      // 8192
    g_Wsp[i] = W_w[(i >> 8) * 512 + (i & 255)];
}

// Le[row, c] = He[row,:] . W_w[c, 256:512] + W_b[c]   (He from fp16 hi/lo)
__global__ void __launch_bounds__(256) le_kernel(const float* __restrict__ W_w,
                                                 const float* __restrict__ W_b) {
    __shared__ float We[32][257];
    int tid = threadIdx.x;
    for (int i = tid; i < 32 * 256; i += 256) {
        int c = i >> 8, g = i & 255;
        We[c][g] = W_w[c * 512 + 256 + g];
    }
    __syncthreads();
    int c = tid & 31, r = tid >> 5;
    int row = blockIdx.x * 8 + r;
    const __half* hh = g_He_hi + (size_t)row * NH;
    const __half* hl = g_He_lo + (size_t)row * NH;
    float acc = 0.f;
#pragma unroll 8
    for (int g = 0; g < 256; ++g) {
        float he = __half2float(hh[g]) + __half2float(hl[g]);
        acc = fmaf(he, We[c][g], acc);
    }
    g_Le[(size_t)row * NC + c] = acc + W_b[c];
}

// ---------------- unified HMMA split-fp16 NT GEMM ----------------
// C[m,n] = sum over products of Ax[m,k]*Bx[n,k], K elems per row (lda=ldb=K).
// P=3: (A0,B0)+(A0,B1)+(A1,B0).  P=1: (A0,B0).
// Tile 128x128, BK=64, 256 threads, 8 warps (2m x 4n).
// Grid: blockIdx.x = M block (fastest -> B-tile L2 reuse), blockIdx.y = N block.
// MODE 0: proj  -> split output to (Oh,Ol) for n<256 else (Oh2,Ol2), +bcat[n]
// MODE 1: G1    -> single fp16 Oh, + aux[n]
// MODE 2: G2    -> fp32 Of, + aux[b*NS*NC + n]
template<int P, int MODE>
__global__ void __launch_bounds__(256) gemm_mma(
    const __half* __restrict__ A0, const __half* __restrict__ A1,
    const __half* __restrict__ B0, const __half* __restrict__ B1,
    long sA, long sB, int K,
    const float* __restrict__ aux,
    __half* __restrict__ Oh, __half* __restrict__ Ol,
    __half* __restrict__ Oh2, __half* __restrict__ Ol2,
    float* __restrict__ Of, int ldc, long sC)
{
    constexpr int NT = (P == 3) ? 4 : 2;              // tiles per stage
    constexpr uint32_t TILE_B = 16384;
    constexpr uint32_t STAGE = NT * TILE_B;

    extern __shared__ char smem[];
    const uint32_t sb = smem_u32(smem);

    const int tid  = threadIdx.x;
    const int wid  = tid >> 5;
    const int lane = tid & 31;
    const int b    = blockIdx.z;
    const int bm   = blockIdx.x * 128;
    const int bn   = blockIdx.y * 128;

    const __half* A0g = A0 + (size_t)b * sA;
    const __half* A1g = (P == 3) ? A1 + (size_t)b * sA : nullptr;
    const __half* B0g = B0 + (size_t)b * sB;
    const __half* B1g = (P == 3) ? B1 + (size_t)b * sB : nullptr;

    const int fr = tid >> 3;            // 0..31
    const int fk = tid & 7;             // 16B unit in 128B row

    const int wm = (wid & 1) * 64;
    const int wn = (wid >> 1) * 32;
    const int lrow = lane & 15;
    const int lhalf = lane >> 4;

    float acc[4][4][4] = {};

    auto fill = [&](int c, int s) {
        const int ko = c * 64;
        const uint32_t base = sb + s * STAGE;
#pragma unroll
        for (int i = 0; i < 4; ++i) {
            int r = fr + i * 32;
            uint32_t d = sw128((uint32_t)(r * 128 + fk * 16));
            cp16(base + d,          A0g + (size_t)(bm + r) * K + ko + fk * 8);
            cp16(base + TILE_B + d, B0g + (size_t)(bn + r) * K + ko + fk * 8);
            if (P == 3) {
                cp16(base + 2 * TILE_B + d, A1g + (size_t)(bm + r) * K + ko + fk * 8);
                cp16(base + 3 * TILE_B + d, B1g + (size_t)(bn + r) * K + ko + fk * 8);
            }
        }
        CP_COMMIT();
    };

    auto compute = [&](int s) {
        const uint32_t a0b = sb + s * STAGE;
        const uint32_t b0b = a0b + TILE_B;
        const uint32_t a1b = a0b + 2 * TILE_B;
        const uint32_t b1b = a0b + 3 * TILE_B;
#pragma unroll
        for (int ks = 0; ks < 4; ++ks) {
            const uint32_t coff = (uint32_t)(ks * 32 + lhalf * 16);
            uint32_t a0f[4][4];
#pragma unroll
            for (int mt = 0; mt < 4; ++mt) {
                int row = wm + mt * 16 + lrow;
                ldsm4(a0f[mt][0], a0f[mt][1], a0f[mt][2], a0f[mt][3],
                      a0b + sw128((uint32_t)(row * 128) + coff));
            }
            uint32_t b0f[2][4];
#pragma unroll
            for (int bp = 0; bp < 2; ++bp) {
                int row = wn + bp * 16 + lrow;
                ldsm4(b0f[bp][0], b0f[bp][1], b0f[bp][2], b0f[bp][3],
                      b0b + sw128((uint32_t)(row * 128) + coff));
            }
#pragma unroll
            for (int mt = 0; mt < 4; ++mt)
#pragma unroll
                for (int nt = 0; nt < 4; ++nt) {
                    int bp = nt >> 1, q = nt & 1;
                    mma16816(acc[mt][nt], a0f[mt], b0f[bp][q], b0f[bp][q + 2]);
                }
            if (P == 3) {
                uint32_t b1f[2][4];
#pragma unroll
                for (int bp = 0; bp < 2; ++bp) {
                    int row = wn + bp * 16 + lrow;
                    ldsm4(b1f[bp][0], b1f[bp][1], b1f[bp][2], b1f[bp][3],
                          b1b + sw128((uint32_t)(row * 128) + coff));
                }
#pragma unroll
                for (int mt = 0; mt < 4; ++mt)
#pragma unroll
                    for (int nt = 0; nt < 4; ++nt) {
                        int bp = nt >> 1, q = nt & 1;
                        mma16816(acc[mt][nt], a0f[mt], b1f[bp][q], b1f[bp][q + 2]);
                    }
                uint32_t a1f[4][4];
#pragma unroll
                for (int mt = 0; mt < 4; ++mt) {
                    int row = wm + mt * 16 + lrow;
                    ldsm4(a1f[mt][0], a1f[mt][1], a1f[mt][2], a1f[mt][3],
                          a1b + sw128((uint32_t)(row * 128) + coff));
                }
#pragma unroll
                for (int mt = 0; mt < 4; ++mt)
#pragma unroll
                    for (int nt = 0; nt < 4; ++nt) {
                        int bp = nt >> 1, q = nt & 1;
                        mma16816(acc[mt][nt], a1f[mt], b0f[bp][q], b0f[bp][q + 2]);
                    }
            }
        }
    };

    const int nchunks = K >> 6;
    fill(0, 0);
    for (int c = 0; c < nchunks; ++c) {
        const int s = c & 1;
        if (c + 1 < nchunks) {
            fill(c + 1, s ^ 1);
            CP_WAIT1();
        } else {
            CP_WAIT0();
        }
        __syncthreads();
        compute(s);
        __syncthreads();
    }

    // ---------------- epilogue ----------------
    const int rbase = bm + wm + (lane >> 2);
    const int cb0 = bn + wn + (lane & 3) * 2;
#pragma unroll
    for (int mt = 0; mt < 4; ++mt)
#pragma unroll
        for (int nt = 0; nt < 4; ++nt) {
            int r0 = rbase + mt * 16;
            int cn = cb0 + nt * 8;
#pragma unroll
            for (int h = 0; h < 2; ++h) {
                int r = r0 + h * 8;
                float v0 = acc[mt][nt][h * 2 + 0];
                float v1 = acc[mt][nt][h * 2 + 1];
                if (MODE == 0) {
                    v0 += aux[cn]; v1 += aux[cn + 1];
                    __half h0, l0, h1, l1;
                    split2h(v0, h0, l0);
                    split2h(v1, h1, l1);
                    __half2 th; th.x = h0; th.y = h1;
                    __half2 tl; tl.x = l0; tl.y = l1;
                    if (cn < NH) {
                        *reinterpret_cast<__half2*>(Oh + (size_t)r * NH + cn) = th;
                        *reinterpret_cast<__half2*>(Ol + (size_t)r * NH + cn) = tl;
                    } else {
                        *reinterpret_cast<__half2*>(Oh2 + (size_t)r * NH + cn - NH) = th;
                        *reinterpret_cast<__half2*>(Ol2 + (size_t)r * NH + cn - NH) = tl;
                    }
                } else if (MODE == 1) {
                    v0 += aux[cn]; v1 += aux[cn + 1];
                    __half2 t; t.x = __float2half_rn(v0); t.y = __float2half_rn(v1);
                    *reinterpret_cast<__half2*>(Oh + (size_t)b * sC + (size_t)r * ldc + cn) = t;
                } else {
                    const float* le = aux + (size_t)b * (NS * NC);
                    float2 t;
                    t.x = v0 + le[cn];
                    t.y = v1 + le[cn + 1];
                    *reinterpret_cast<float2*>(Of + (size_t)b * sC + (size_t)r * ldc + cn) = t;
                }
            }
        }
}

// ---------------- launch ----------------
extern "C" void kernel_launch(void* const* d_in, const int* in_sizes, int n_in,
                              void* d_out, int out_size) {
    const float* seq  = (const float*)d_in[0];
    const float* U    = (const float*)d_in[1];
    const float* W_w  = (const float*)d_in[2];
    const float* W_b  = (const float*)d_in[3];
    const float* Ws_w = (const float*)d_in[4];
    const float* Ws_b = (const float*)d_in[5];
    const float* We_w = (const float*)d_in[6];
    const float* We_b = (const float*)d_in[7];
    float* out = (float*)d_out;

    __half *seq_hi, *seq_lo, *Wc_hi, *Wc_lo, *Hs_hi, *Hs_lo, *He_hi, *He_lo, *Ur_hi, *M;
    float *bcat, *Le, *Wsp;
    cudaGetSymbolAddress((void**)&seq_hi, g_seq_hi);
    cudaGetSymbolAddress((void**)&seq_lo, g_seq_lo);
    cudaGetSymbolAddress((void**)&Wc_hi,  g_Wcat_hi);
    cudaGetSymbolAddress((void**)&Wc_lo,  g_Wcat_lo);
    cudaGetSymbolAddress((void**)&bcat,   g_bcat);
    cudaGetSymbolAddress((void**)&Hs_hi,  g_Hs_hi);
    cudaGetSymbolAddress((void**)&Hs_lo,  g_Hs_lo);
    cudaGetSymbolAddress((void**)&He_hi,  g_He_hi);
    cudaGetSymbolAddress((void**)&He_lo,  g_He_lo);
    cudaGetSymbolAddress((void**)&Ur_hi,  g_Ur_hi);
    cudaGetSymbolAddress((void**)&M,      g_M);
    cudaGetSymbolAddress((void**)&Le,     g_Le);
    cudaGetSymbolAddress((void**)&Wsp,    g_Wsp);

    const int SMEM_P3 = 2 * 4 * 16384;   // 128 KB
    const int SMEM_P1 = 2 * 2 * 16384;   // 64 KB
    cudaFuncSetAttribute(gemm_mma<3, 0>, cudaFuncAttributeMaxDynamicSharedMemorySize, SMEM_P3);
    cudaFuncSetAttribute(gemm_mma<1, 1>, cudaFuncAttributeMaxDynamicSharedMemorySize, SMEM_P1);
    cudaFuncSetAttribute(gemm_mma<1, 2>, cudaFuncAttributeMaxDynamicSharedMemorySize, SMEM_P1);

    // prep
    rearrange_U_kernel<<<(NC * NH * NH) / 256, 256>>>(U);
    wsp_kernel<<<(NC * NH) / 256, 256>>>(W_w);
    wcat_kernel<<<(2 * NH * ND) / 256, 256>>>(Ws_w, We_w, Ws_b, We_b);
    split_seq_kernel<<<(NB * NS * ND / 2) / 256, 256>>>(seq);

    // fused projections: [Hs | He] = seq @ Wcat^T + bcat   (M=4096, N=512, K=768)
    gemm_mma<3, 0><<<dim3(32, 4, 1), 256, SMEM_P3>>>(
        seq_hi, seq_lo, Wc_hi, Wc_lo, 0L, 0L, ND,
        bcat, Hs_hi, Hs_lo, He_hi, He_lo, nullptr, NH, 0L);

    le_kernel<<<(NB * NS) / 8, 256>>>(W_w, W_b);

    // GEMM1: M[b, e, (c,h)] = He_hi_b @ Ur_hi^T + W_s -> fp16  (512 x 8192 x 256)
    gemm_mma<1, 1><<<dim3(4, 64, NB), 256, SMEM_P1>>>(
        He_hi, nullptr, Ur_hi, nullptr,
        (long)NS * NH, 0L, NH,
        Wsp, M, nullptr, nullptr, nullptr, nullptr, NC * NH, (long)NS * NC * NH);

    // GEMM2: out[b, s, (e,c)] = Hs_hi_b @ M_b^T + Le -> fp32   (512 x 16384 x 256)
    gemm_mma<1, 2><<<dim3(4, 128, NB), 256, SMEM_P1>>>(
        Hs_hi, nullptr, M, nullptr,
        (long)NS * NH, (long)NS * NC * NH, NH,
        Le, nullptr, nullptr, nullptr, nullptr, out, NS * NC, (long)NS * NS * NC);
}

// round 12
// speedup vs baseline: 5.4019x; 1.0857x over previous
#include <cuda_runtime.h>
#include <cuda_fp16.h>
#include <cstdint>

#define NB 8
#define NS 512
#define ND 768
#define NH 256
#define NC 32

// ---------------- scratch (device globals) ----------------
__device__ __align__(16) __half g_seq_hi[NB * NS * ND];
__device__ __align__(16) __half g_seq_lo[NB * NS * ND];
__device__ __align__(16) __half g_Wcat_hi[2 * NH * ND];   // rows 0-255 Ws_w, 256-511 We_w
__device__ __align__(16) __half g_Wcat_lo[2 * NH * ND];
__device__ float g_bcat[2 * NH];
__device__ __align__(16) __half g_Hs_hi[NB * NS * NH];
__device__ __align__(16) __half g_Hs_lo[NB * NS * NH];
__device__ __align__(16) __half g_He_hi[NB * NS * NH];
__device__ __align__(16) __half g_He_lo[NB * NS * NH];
__device__ __align__(16) __half g_Ur_hi[NC * NH * NH];
__device__ __align__(16) __half g_M[(size_t)NB * NS * NC * NH];   // single fp16
__device__ float g_Le[NB * NS * NC];
__device__ float g_Wsp[NC * NH];

// ---------------- helpers ----------------
__device__ __forceinline__ uint32_t smem_u32(const void* p) {
    uint32_t a;
    asm("{ .reg .u64 t; cvta.to.shared.u64 t, %1; cvt.u32.u64 %0, t; }" : "=r"(a) : "l"(p));
    return a;
}
__device__ __forceinline__ void cp16(uint32_t s, const void* g) {
    asm volatile("cp.async.cg.shared.global [%0], [%1], 16;" :: "r"(s), "l"(g));
}
#define CP_COMMIT() asm volatile("cp.async.commit_group;" ::: "memory")
#define CP_WAIT1()  asm volatile("cp.async.wait_group 1;" ::: "memory")
#define CP_WAIT0()  asm volatile("cp.async.wait_group 0;" ::: "memory")

__device__ __forceinline__ void ldsm4(uint32_t& r0, uint32_t& r1, uint32_t& r2, uint32_t& r3, uint32_t a) {
    asm volatile("ldmatrix.sync.aligned.m8n8.x4.shared.b16 {%0,%1,%2,%3}, [%4];"
                 : "=r"(r0), "=r"(r1), "=r"(r2), "=r"(r3) : "r"(a));
}
__device__ __forceinline__ void mma16816(float* c, const uint32_t* a, uint32_t b0, uint32_t b1) {
    asm volatile("mma.sync.aligned.m16n8k16.row.col.f32.f16.f16.f32 "
                 "{%0,%1,%2,%3}, {%4,%5,%6,%7}, {%8,%9}, {%0,%1,%2,%3};"
                 : "+f"(c[0]), "+f"(c[1]), "+f"(c[2]), "+f"(c[3])
                 : "r"(a[0]), "r"(a[1]), "r"(a[2]), "r"(a[3]), "r"(b0), "r"(b1));
}
__device__ __forceinline__ uint32_t sw128(uint32_t off) {
    return off ^ ((off >> 3) & 0x70);
}
__device__ __forceinline__ void split2h(float v, __half& h, __half& l) {
    h = __float2half_rn(v);
    l = __float2half_rn(v - __half2float(h));
}

// ---------------- prep kernels ----------------
__global__ void split_seq_kernel(const float* __restrict__ seq) {
    int i = blockIdx.x * 256 + threadIdx.x;      // over element pairs
    float2 v = reinterpret_cast<const float2*>(seq)[i];
    __half h0, l0, h1, l1;
    split2h(v.x, h0, l0);
    split2h(v.y, h1, l1);
    __half2 hh; hh.x = h0; hh.y = h1;
    __half2 ll; ll.x = l0; ll.y = l1;
    reinterpret_cast<__half2*>(g_seq_hi)[i] = hh;
    reinterpret_cast<__half2*>(g_seq_lo)[i] = ll;
}

__global__ void wcat_kernel(const float* __restrict__ Ws_w, const float* __restrict__ We_w,
                            const float* __restrict__ Ws_b, const float* __restrict__ We_b) {
    int i = blockIdx.x * 256 + threadIdx.x;      // 512*768
    int n = i / ND, d = i - n * ND;
    float v = (n < NH) ? Ws_w[n * ND + d] : We_w[(n - NH) * ND + d];
    __half h, l;
    split2h(v, h, l);
    g_Wcat_hi[i] = h;
    g_Wcat_lo[i] = l;
    if (i < 2 * NH) g_bcat[i] = (i < NH) ? Ws_b[i] : We_b[i - NH];
}

__global__ void rearrange_U_kernel(const float* __restrict__ U) {
    int idx = blockIdx.x * 256 + threadIdx.x;    // NC*NH*NH
    int g = idx & 255, h = (idx >> 8) & 255, c = idx >> 16;
    float u = U[(size_t)h * (NC * NH) + c * NH + g];
    g_Ur_hi[idx] = __float2half_rn(u);
}

__global__ void wsp_kernel(const float* __restrict__ W_w) {
    int i = blockIdx.x * 256 + threadIdx.x;      // 8192
    g_Wsp[i] = W_w[(i >> 8) * 512 + (i & 255)];
}

// Le[row, c] = He[row,:] . W_w[c, 256:512] + W_b[c]   (He from fp16 hi/lo)
__global__ void __launch_bounds__(256) le_kernel(const float* __restrict__ W_w,
                                                 const float* __restrict__ W_b) {
    __shared__ float We[32][257];
    int tid = threadIdx.x;
    for (int i = tid; i < 32 * 256; i += 256) {
        int c = i >> 8, g = i & 255;
        We[c][g] = W_w[c * 512 + 256 + g];
    }
    __syncthreads();
    int c = tid & 31, r = tid >> 5;
    int row = blockIdx.x * 8 + r;
    const __half* hh = g_He_hi + (size_t)row * NH;
    const __half* hl = g_He_lo + (size_t)row * NH;
    float acc = 0.f;
#pragma unroll 8
    for (int g = 0; g < 256; ++g) {
        float he = __half2float(hh[g]) + __half2float(hl[g]);
        acc = fmaf(he, We[c][g], acc);
    }
    g_Le[(size_t)row * NC + c] = acc + W_b[c];
}

// ---------------- unified HMMA split-fp16 NT GEMM ----------------
// C[m,n] = sum over products of Ax[m,k]*Bx[n,k], K elems per row (lda=ldb=K).
// P=3: (A0,B0)+(A0,B1)+(A1,B0).  P=1: (A0,B0).
// Tile 128xTN (TN = 128 or 256), BK=64, 256 threads, 8 warps (2m x 4n), warp tile 64x(TN/4).
// Grid: blockIdx.x = M block (fastest -> B-tile L2 reuse), blockIdx.y = N block.
// MODE 0: proj  -> split output to (Oh,Ol) for n<256 else (Oh2,Ol2), +bcat[n]
// MODE 1: G1    -> single fp16 Oh, + aux[n]
// MODE 2: G2    -> fp32 Of (streaming stores), + aux[b*NS*NC + n]
template<int P, int MODE, int TN>
__global__ void __launch_bounds__(256) gemm_mma(
    const __half* __restrict__ A0, const __half* __restrict__ A1,
    const __half* __restrict__ B0, const __half* __restrict__ B1,
    long sA, long sB, int K,
    const float* __restrict__ aux,
    __half* __restrict__ Oh, __half* __restrict__ Ol,
    __half* __restrict__ Oh2, __half* __restrict__ Ol2,
    float* __restrict__ Of, int ldc, long sC)
{
    constexpr uint32_t TILE_A = 16384;           // 128 rows x 128B
    constexpr uint32_t TILE_BB = TN * 128;       // TN rows x 128B
    constexpr uint32_t OFF_B0 = TILE_A;
    constexpr uint32_t OFF_A1 = TILE_A + TILE_BB;
    constexpr uint32_t OFF_B1 = 2 * TILE_A + TILE_BB;
    constexpr uint32_t STAGE = (P == 3) ? 2 * (TILE_A + TILE_BB) : (TILE_A + TILE_BB);
    constexpr int NBP = TN / 64;                 // B ldsm4 loads per ks per warp
    constexpr int NNT = TN / 32;                 // n-subtiles (8 cols each) per warp

    extern __shared__ char smem[];
    const uint32_t sb = smem_u32(smem);

    const int tid  = threadIdx.x;
    const int wid  = tid >> 5;
    const int lane = tid & 31;
    const int b    = blockIdx.z;
    const int bm   = blockIdx.x * 128;
    const int bn   = blockIdx.y * TN;

    const __half* A0g = A0 + (size_t)b * sA;
    const __half* A1g = (P == 3) ? A1 + (size_t)b * sA : nullptr;
    const __half* B0g = B0 + (size_t)b * sB;
    const __half* B1g = (P == 3) ? B1 + (size_t)b * sB : nullptr;

    const int fr = tid >> 3;            // 0..31
    const int fk = tid & 7;             // 16B unit in 128B row

    const int wm = (wid & 1) * 64;
    const int wn = (wid >> 1) * (TN / 4);
    const int lrow = lane & 15;
    const int lhalf = lane >> 4;

    float acc[4][NNT][4] = {};

    auto fill = [&](int c, int s) {
        const int ko = c * 64;
        const uint32_t base = sb + s * STAGE;
#pragma unroll
        for (int i = 0; i < 4; ++i) {
            int r = fr + i * 32;
            uint32_t d = sw128((uint32_t)(r * 128 + fk * 16));
            cp16(base + d, A0g + (size_t)(bm + r) * K + ko + fk * 8);
            if (P == 3)
                cp16(base + OFF_A1 + d, A1g + (size_t)(bm + r) * K + ko + fk * 8);
        }
#pragma unroll
        for (int i = 0; i < TN / 32; ++i) {
            int r = fr + i * 32;
            uint32_t d = sw128((uint32_t)(r * 128 + fk * 16));
            cp16(base + OFF_B0 + d, B0g + (size_t)(bn + r) * K + ko + fk * 8);
            if (P == 3)
                cp16(base + OFF_B1 + d, B1g + (size_t)(bn + r) * K + ko + fk * 8);
        }
        CP_COMMIT();
    };

    auto compute = [&](int s) {
        const uint32_t a0b = sb + s * STAGE;
        const uint32_t b0b = a0b + OFF_B0;
        const uint32_t a1b = a0b + OFF_A1;
        const uint32_t b1b = a0b + OFF_B1;
#pragma unroll
        for (int ks = 0; ks < 4; ++ks) {
            const uint32_t coff = (uint32_t)(ks * 32 + lhalf * 16);
            uint32_t a0f[4][4];
#pragma unroll
            for (int mt = 0; mt < 4; ++mt) {
                int row = wm + mt * 16 + lrow;
                ldsm4(a0f[mt][0], a0f[mt][1], a0f[mt][2], a0f[mt][3],
                      a0b + sw128((uint32_t)(row * 128) + coff));
            }
            uint32_t b0f[NBP][4];
#pragma unroll
            for (int bp = 0; bp < NBP; ++bp) {
                int row = wn + bp * 16 + lrow;
                ldsm4(b0f[bp][0], b0f[bp][1], b0f[bp][2], b0f[bp][3],
                      b0b + sw128((uint32_t)(row * 128) + coff));
            }
#pragma unroll
            for (int mt = 0; mt < 4; ++mt)
#pragma unroll
                for (int nt = 0; nt < NNT; ++nt) {
                    int bp = nt >> 1, q = nt & 1;
                    mma16816(acc[mt][nt], a0f[mt], b0f[bp][q], b0f[bp][q + 2]);
                }
            if (P == 3) {
                uint32_t b1f[NBP][4];
#pragma unroll
                for (int bp = 0; bp < NBP; ++bp) {
                    int row = wn + bp * 16 + lrow;
                    ldsm4(b1f[bp][0], b1f[bp][1], b1f[bp][2], b1f[bp][3],
                          b1b + sw128((uint32_t)(row * 128) + coff));
                }
#pragma unroll
                for (int mt = 0; mt < 4; ++mt)
#pragma unroll
                    for (int nt = 0; nt < NNT; ++nt) {
                        int bp = nt >> 1, q = nt & 1;
                        mma16816(acc[mt][nt], a0f[mt], b1f[bp][q], b1f[bp][q + 2]);
                    }
                uint32_t a1f[4][4];
#pragma unroll
                for (int mt = 0; mt < 4; ++mt) {
                    int row = wm + mt * 16 + lrow;
                    ldsm4(a1f[mt][0], a1f[mt][1], a1f[mt][2], a1f[mt][3],
                          a1b + sw128((uint32_t)(row * 128) + coff));
                }
#pragma unroll
                for (int mt = 0; mt < 4; ++mt)
#pragma unroll
                    for (int nt = 0; nt < NNT; ++nt) {
                        int bp = nt >> 1, q = nt & 1;
                        mma16816(acc[mt][nt], a1f[mt], b0f[bp][q], b0f[bp][q + 2]);
                    }
            }
        }
    };

    const int nchunks = K >> 6;
    fill(0, 0);
    for (int c = 0; c < nchunks; ++c) {
        const int s = c & 1;
        if (c + 1 < nchunks) {
            fill(c + 1, s ^ 1);
            CP_WAIT1();
        } else {
            CP_WAIT0();
        }
        __syncthreads();
        compute(s);
        __syncthreads();
    }

    // ---------------- epilogue ----------------
    const int rbase = bm + wm + (lane >> 2);
    const int cb0 = bn + wn + (lane & 3) * 2;
#pragma unroll
    for (int mt = 0; mt < 4; ++mt)
#pragma unroll
        for (int nt = 0; nt < NNT; ++nt) {
            int r0 = rbase + mt * 16;
            int cn = cb0 + nt * 8;
#pragma unroll
            for (int h = 0; h < 2; ++h) {
                int r = r0 + h * 8;
                float v0 = acc[mt][nt][h * 2 + 0];
                float v1 = acc[mt][nt][h * 2 + 1];
                if (MODE == 0) {
                    v0 += aux[cn]; v1 += aux[cn + 1];
                    __half h0, l0, h1, l1;
                    split2h(v0, h0, l0);
                    split2h(v1, h1, l1);
                    __half2 th; th.x = h0; th.y = h1;
                    __half2 tl; tl.x = l0; tl.y = l1;
                    if (cn < NH) {
                        *reinterpret_cast<__half2*>(Oh + (size_t)r * NH + cn) = th;
                        *reinterpret_cast<__half2*>(Ol + (size_t)r * NH + cn) = tl;
                    } else {
                        *reinterpret_cast<__half2*>(Oh2 + (size_t)r * NH + cn - NH) = th;
                        *reinterpret_cast<__half2*>(Ol2 + (size_t)r * NH + cn - NH) = tl;
                    }
                } else if (MODE == 1) {
                    v0 += aux[cn]; v1 += aux[cn + 1];
                    __half2 t; t.x = __float2half_rn(v0); t.y = __float2half_rn(v1);
                    *reinterpret_cast<__half2*>(Oh + (size_t)b * sC + (size_t)r * ldc + cn) = t;
                } else {
                    const float* le = aux + (size_t)b * (NS * NC);
                    float2 t;
                    t.x = v0 + le[cn];
                    t.y = v1 + le[cn + 1];
                    __stcs(reinterpret_cast<float2*>(Of + (size_t)b * sC + (size_t)r * ldc + cn), t);
                }
            }
        }
}

// ---------------- launch ----------------
extern "C" void kernel_launch(void* const* d_in, const int* in_sizes, int n_in,
                              void* d_out, int out_size) {
    const float* seq  = (const float*)d_in[0];
    const float* U    = (const float*)d_in[1];
    const float* W_w  = (const float*)d_in[2];
    const float* W_b  = (const float*)d_in[3];
    const float* Ws_w = (const float*)d_in[4];
    const float* Ws_b = (const float*)d_in[5];
    const float* We_w = (const float*)d_in[6];
    const float* We_b = (const float*)d_in[7];
    float* out = (float*)d_out;

    __half *seq_hi, *seq_lo, *Wc_hi, *Wc_lo, *Hs_hi, *Hs_lo, *He_hi, *He_lo, *Ur_hi, *M;
    float *bcat, *Le, *Wsp;
    cudaGetSymbolAddress((void**)&seq_hi, g_seq_hi);
    cudaGetSymbolAddress((void**)&seq_lo, g_seq_lo);
    cudaGetSymbolAddress((void**)&Wc_hi,  g_Wcat_hi);
    cudaGetSymbolAddress((void**)&Wc_lo,  g_Wcat_lo);
    cudaGetSymbolAddress((void**)&bcat,   g_bcat);
    cudaGetSymbolAddress((void**)&Hs_hi,  g_Hs_hi);
    cudaGetSymbolAddress((void**)&Hs_lo,  g_Hs_lo);
    cudaGetSymbolAddress((void**)&He_hi,  g_He_hi);
    cudaGetSymbolAddress((void**)&He_lo,  g_He_lo);
    cudaGetSymbolAddress((void**)&Ur_hi,  g_Ur_hi);
    cudaGetSymbolAddress((void**)&M,      g_M);
    cudaGetSymbolAddress((void**)&Le,     g_Le);
    cudaGetSymbolAddress((void**)&Wsp,    g_Wsp);

    const int SMEM_PROJ = 2 * 2 * (16384 + 16384);      // 128 KB
    const int SMEM_BIG  = 2 * (16384 + 256 * 128);      // 96 KB
    cudaFuncSetAttribute(gemm_mma<3, 0, 128>, cudaFuncAttributeMaxDynamicSharedMemorySize, SMEM_PROJ);
    cudaFuncSetAttribute(gemm_mma<1, 1, 256>, cudaFuncAttributeMaxDynamicSharedMemorySize, SMEM_BIG);
    cudaFuncSetAttribute(gemm_mma<1, 2, 256>, cudaFuncAttributeMaxDynamicSharedMemorySize, SMEM_BIG);

    // prep
    rearrange_U_kernel<<<(NC * NH * NH) / 256, 256>>>(U);
    wsp_kernel<<<(NC * NH) / 256, 256>>>(W_w);
    wcat_kernel<<<(2 * NH * ND) / 256, 256>>>(Ws_w, We_w, Ws_b, We_b);
    split_seq_kernel<<<(NB * NS * ND / 2) / 256, 256>>>(seq);

    // fused projections: [Hs | He] = seq @ Wcat^T + bcat   (M=4096, N=512, K=768)
    gemm_mma<3, 0, 128><<<dim3(32, 4, 1), 256, SMEM_PROJ>>>(
        seq_hi, seq_lo, Wc_hi, Wc_lo, 0L, 0L, ND,
        bcat, Hs_hi, Hs_lo, He_hi, He_lo, nullptr, NH, 0L);

    le_kernel<<<(NB * NS) / 8, 256>>>(W_w, W_b);

    // GEMM1: M[b, e, (c,h)] = He_hi_b @ Ur_hi^T + W_s -> fp16  (512 x 8192 x 256)
    gemm_mma<1, 1, 256><<<dim3(4, 32, NB), 256, SMEM_BIG>>>(
        He_hi, nullptr, Ur_hi, nullptr,
        (long)NS * NH, 0L, NH,
        Wsp, M, nullptr, nullptr, nullptr, nullptr, NC * NH, (long)NS * NC * NH);

    // GEMM2: out[b, s, (e,c)] = Hs_hi_b @ M_b^T + Le -> fp32   (512 x 16384 x 256)
    gemm_mma<1, 2, 256><<<dim3(4, 64, NB), 256, SMEM_BIG>>>(
        Hs_hi, nullptr, M, nullptr,
        (long)NS * NH, (long)NS * NC * NH, NH,
        Le, nullptr, nullptr, nullptr, nullptr, out, NS * NC, (long)NS * NS * NC);
}

// round 13
// speedup vs baseline: 5.7097x; 1.0570x over previous
#include <cuda_runtime.h>
#include <cuda_fp16.h>
#include <cstdint>

#define NB 8
#define NS 512
#define ND 768
#define NH 256
#define NC 32

// ---------------- scratch (device globals) ----------------
__device__ __align__(16) __half g_seq_hi[NB * NS * ND];
__device__ __align__(16) __half g_seq_lo[NB * NS * ND];
__device__ __align__(16) __half g_Wcat_hi[2 * NH * ND];   // rows 0-255 Ws_w, 256-511 We_w
__device__ float g_bcat[2 * NH];
__device__ __align__(16) __half g_Hs_hi[NB * NS * NH];
__device__ __align__(16) __half g_Hs_lo[NB * NS * NH];
__device__ __align__(16) __half g_He_hi[NB * NS * NH];
__device__ __align__(16) __half g_He_lo[NB * NS * NH];
__device__ __align__(16) __half g_Ur_hi[NC * NH * NH];
__device__ __align__(16) __half g_M[(size_t)NB * NS * NC * NH];   // single fp16
__device__ float g_Le[NB * NS * NC];
__device__ float g_Wsp[NC * NH];

// ---------------- helpers ----------------
__device__ __forceinline__ uint32_t smem_u32(const void* p) {
    uint32_t a;
    asm("{ .reg .u64 t; cvta.to.shared.u64 t, %1; cvt.u32.u64 %0, t; }" : "=r"(a) : "l"(p));
    return a;
}
__device__ __forceinline__ void cp16(uint32_t s, const void* g) {
    asm volatile("cp.async.cg.shared.global [%0], [%1], 16;" :: "r"(s), "l"(g));
}
#define CP_COMMIT() asm volatile("cp.async.commit_group;" ::: "memory")
#define CP_WAIT2()  asm volatile("cp.async.wait_group 2;" ::: "memory")
#define CP_WAIT1()  asm volatile("cp.async.wait_group 1;" ::: "memory")
#define CP_WAIT0()  asm volatile("cp.async.wait_group 0;" ::: "memory")

__device__ __forceinline__ void ldsm4(uint32_t& r0, uint32_t& r1, uint32_t& r2, uint32_t& r3, uint32_t a) {
    asm volatile("ldmatrix.sync.aligned.m8n8.x4.shared.b16 {%0,%1,%2,%3}, [%4];"
                 : "=r"(r0), "=r"(r1), "=r"(r2), "=r"(r3) : "r"(a));
}
__device__ __forceinline__ void mma16816(float* c, const uint32_t* a, uint32_t b0, uint32_t b1) {
    asm volatile("mma.sync.aligned.m16n8k16.row.col.f32.f16.f16.f32 "
                 "{%0,%1,%2,%3}, {%4,%5,%6,%7}, {%8,%9}, {%0,%1,%2,%3};"
                 : "+f"(c[0]), "+f"(c[1]), "+f"(c[2]), "+f"(c[3])
                 : "r"(a[0]), "r"(a[1]), "r"(a[2]), "r"(a[3]), "r"(b0), "r"(b1));
}
__device__ __forceinline__ uint32_t sw128(uint32_t off) {
    return off ^ ((off >> 3) & 0x70);
}
__device__ __forceinline__ void split2h(float v, __half& h, __half& l) {
    h = __float2half_rn(v);
    l = __float2half_rn(v - __half2float(h));
}

// ---------------- fused prep kernel (grid-sectioned) ----------------
#define BLK_SPLIT  6144                      // NB*NS*ND/2 /256
#define BLK_U      8192                      // NC*NH*NH /256
#define BLK_WCAT   1536                      // 2*NH*ND /256
#define BLK_WSP    32                        // NC*NH /256
__global__ void prep_kernel(const float* __restrict__ seq, const float* __restrict__ U,
                            const float* __restrict__ W_w,
                            const float* __restrict__ Ws_w, const float* __restrict__ We_w,
                            const float* __restrict__ Ws_b, const float* __restrict__ We_b) {
    int blk = blockIdx.x;
    int tid = threadIdx.x;
    if (blk < BLK_SPLIT) {
        int i = blk * 256 + tid;
        float2 v = reinterpret_cast<const float2*>(seq)[i];
        __half h0, l0, h1, l1;
        split2h(v.x, h0, l0);
        split2h(v.y, h1, l1);
        __half2 hh; hh.x = h0; hh.y = h1;
        __half2 ll; ll.x = l0; ll.y = l1;
        reinterpret_cast<__half2*>(g_seq_hi)[i] = hh;
        reinterpret_cast<__half2*>(g_seq_lo)[i] = ll;
    } else if (blk < BLK_SPLIT + BLK_U) {
        int idx = (blk - BLK_SPLIT) * 256 + tid;
        int g = idx & 255, h = (idx >> 8) & 255, c = idx >> 16;
        g_Ur_hi[idx] = __float2half_rn(U[(size_t)h * (NC * NH) + c * NH + g]);
    } else if (blk < BLK_SPLIT + BLK_U + BLK_WCAT) {
        int i = (blk - BLK_SPLIT - BLK_U) * 256 + tid;
        int n = i / ND, d = i - n * ND;
        float v = (n < NH) ? Ws_w[n * ND + d] : We_w[(n - NH) * ND + d];
        g_Wcat_hi[i] = __float2half_rn(v);
        if (i < 2 * NH) g_bcat[i] = (i < NH) ? Ws_b[i] : We_b[i - NH];
    } else {
        int i = (blk - BLK_SPLIT - BLK_U - BLK_WCAT) * 256 + tid;
        g_Wsp[i] = W_w[(i >> 8) * 512 + (i & 255)];
    }
}

// Le[row, c] = He[row,:] . W_w[c, 256:512] + W_b[c]   (He from fp16 hi/lo)
__global__ void __launch_bounds__(256) le_kernel(const float* __restrict__ W_w,
                                                 const float* __restrict__ W_b) {
    __shared__ float We[32][258];
    int tid = threadIdx.x;
    for (int i = tid; i < 32 * 256; i += 256) {
        int c = i >> 8, g = i & 255;
        We[c][g] = W_w[c * 512 + 256 + g];
    }
    __syncthreads();
    int c = tid & 31, r = tid >> 5;
    int row = blockIdx.x * 8 + r;
    const __half2* hh = reinterpret_cast<const __half2*>(g_He_hi + (size_t)row * NH);
    const __half2* hl = reinterpret_cast<const __half2*>(g_He_lo + (size_t)row * NH);
    float acc = 0.f;
#pragma unroll 8
    for (int g = 0; g < 128; ++g) {
        float2 h2 = __half22float2(hh[g]);
        float2 l2 = __half22float2(hl[g]);
        acc = fmaf(h2.x + l2.x, We[c][2 * g], acc);
        acc = fmaf(h2.y + l2.y, We[c][2 * g + 1], acc);
    }
    g_Le[(size_t)row * NC + c] = acc + W_b[c];
}

// ---------------- unified HMMA split-fp16 NT GEMM ----------------
// P=2: (A0,B0)+(A1,B0).  P=1: (A0,B0).
// Tile 128xTN, BK=64, 256 threads, 8 warps (2m x 4n), warp tile 64x(TN/4), ST pipeline stages.
// Grid: blockIdx.x = M block (fastest -> B-tile L2 reuse), blockIdx.y = N block.
// MODE 0: proj  -> split output to (Oh,Ol) for n<256 else (Oh2,Ol2), +bcat[n]
// MODE 1: G1    -> single fp16 Oh, + aux[n]
// MODE 2: G2    -> fp32 Of (streaming stores), + aux[b*NS*NC + n]
template<int P, int MODE, int TN, int ST>
__global__ void __launch_bounds__(256) gemm_mma(
    const __half* __restrict__ A0, const __half* __restrict__ A1,
    const __half* __restrict__ B0,
    long sA, long sB, int K,
    const float* __restrict__ aux,
    __half* __restrict__ Oh, __half* __restrict__ Ol,
    __half* __restrict__ Oh2, __half* __restrict__ Ol2,
    float* __restrict__ Of, int ldc, long sC)
{
    constexpr uint32_t TILE_A = 16384;           // 128 rows x 128B
    constexpr uint32_t TILE_BB = TN * 128;       // TN rows x 128B
    constexpr uint32_t OFF_B0 = TILE_A;
    constexpr uint32_t OFF_A1 = TILE_A + TILE_BB;
    constexpr uint32_t STAGE = (P == 2) ? (2 * TILE_A + TILE_BB) : (TILE_A + TILE_BB);
    constexpr int NBP = TN / 64;                 // B ldsm4 loads per ks per warp
    constexpr int NNT = TN / 32;                 // n-subtiles (8 cols each) per warp

    extern __shared__ char smem[];
    const uint32_t sb = smem_u32(smem);

    const int tid  = threadIdx.x;
    const int wid  = tid >> 5;
    const int lane = tid & 31;
    const int b    = blockIdx.z;
    const int bm   = blockIdx.x * 128;
    const int bn   = blockIdx.y * TN;

    const __half* A0g = A0 + (size_t)b * sA;
    const __half* A1g = (P == 2) ? A1 + (size_t)b * sA : nullptr;
    const __half* B0g = B0 + (size_t)b * sB;

    const int fr = tid >> 3;            // 0..31
    const int fk = tid & 7;             // 16B unit in 128B row

    const int wm = (wid & 1) * 64;
    const int wn = (wid >> 1) * (TN / 4);
    const int lrow = lane & 15;
    const int lhalf = lane >> 4;

    float acc[4][NNT][4] = {};

    auto fill = [&](int c, int s) {
        const int ko = c * 64;
        const uint32_t base = sb + s * STAGE;
#pragma unroll
        for (int i = 0; i < 4; ++i) {
            int r = fr + i * 32;
            uint32_t d = sw128((uint32_t)(r * 128 + fk * 16));
            cp16(base + d, A0g + (size_t)(bm + r) * K + ko + fk * 8);
            if (P == 2)
                cp16(base + OFF_A1 + d, A1g + (size_t)(bm + r) * K + ko + fk * 8);
        }
#pragma unroll
        for (int i = 0; i < TN / 32; ++i) {
            int r = fr + i * 32;
            uint32_t d = sw128((uint32_t)(r * 128 + fk * 16));
            cp16(base + OFF_B0 + d, B0g + (size_t)(bn + r) * K + ko + fk * 8);
        }
        CP_COMMIT();
    };

    auto compute = [&](int s) {
        const uint32_t a0b = sb + s * STAGE;
        const uint32_t b0b = a0b + OFF_B0;
        const uint32_t a1b = a0b + OFF_A1;
#pragma unroll
        for (int ks = 0; ks < 4; ++ks) {
            const uint32_t coff = (uint32_t)(ks * 32 + lhalf * 16);
            uint32_t a0f[4][4];
#pragma unroll
            for (int mt = 0; mt < 4; ++mt) {
                int row = wm + mt * 16 + lrow;
                ldsm4(a0f[mt][0], a0f[mt][1], a0f[mt][2], a0f[mt][3],
                      a0b + sw128((uint32_t)(row * 128) + coff));
            }
            uint32_t b0f[NBP][4];
#pragma unroll
            for (int bp = 0; bp < NBP; ++bp) {
                int row = wn + bp * 16 + lrow;
                ldsm4(b0f[bp][0], b0f[bp][1], b0f[bp][2], b0f[bp][3],
                      b0b + sw128((uint32_t)(row * 128) + coff));
            }
#pragma unroll
            for (int mt = 0; mt < 4; ++mt)
#pragma unroll
                for (int nt = 0; nt < NNT; ++nt) {
                    int bp = nt >> 1, q = nt & 1;
                    mma16816(acc[mt][nt], a0f[mt], b0f[bp][q], b0f[bp][q + 2]);
                }
            if (P == 2) {
                uint32_t a1f[4][4];
#pragma unroll
                for (int mt = 0; mt < 4; ++mt) {
                    int row = wm + mt * 16 + lrow;
                    ldsm4(a1f[mt][0], a1f[mt][1], a1f[mt][2], a1f[mt][3],
                          a1b + sw128((uint32_t)(row * 128) + coff));
                }
#pragma unroll
                for (int mt = 0; mt < 4; ++mt)
#pragma unroll
                    for (int nt = 0; nt < NNT; ++nt) {
                        int bp = nt >> 1, q = nt & 1;
                        mma16816(acc[mt][nt], a1f[mt], b0f[bp][q], b0f[bp][q + 2]);
                    }
            }
        }
    };

    const int nchunks = K >> 6;
    fill(0, 0);
    if (ST == 3 && nchunks > 1) fill(1, 1);
    for (int c = 0; c < nchunks; ++c) {
        const int s = c % ST;
        const int nf = c + ST - 1;
        if (nf < nchunks) {
            fill(nf, nf % ST);
            if (ST == 3) CP_WAIT2(); else CP_WAIT1();
        } else if (c + 1 < nchunks) {
            CP_WAIT1();
        } else {
            CP_WAIT0();
        }
        __syncthreads();
        compute(s);
        __syncthreads();
    }

    // ---------------- epilogue ----------------
    const int rbase = bm + wm + (lane >> 2);
    const int cb0 = bn + wn + (lane & 3) * 2;
#pragma unroll
    for (int mt = 0; mt < 4; ++mt)
#pragma unroll
        for (int nt = 0; nt < NNT; ++nt) {
            int r0 = rbase + mt * 16;
            int cn = cb0 + nt * 8;
#pragma unroll
            for (int h = 0; h < 2; ++h) {
                int r = r0 + h * 8;
                float v0 = acc[mt][nt][h * 2 + 0];
                float v1 = acc[mt][nt][h * 2 + 1];
                if (MODE == 0) {
                    v0 += aux[cn]; v1 += aux[cn + 1];
                    __half h0, l0, h1, l1;
                    split2h(v0, h0, l0);
                    split2h(v1, h1, l1);
                    __half2 th; th.x = h0; th.y = h1;
                    __half2 tl; tl.x = l0; tl.y = l1;
                    if (cn < NH) {
                        *reinterpret_cast<__half2*>(Oh + (size_t)r * NH + cn) = th;
                        *reinterpret_cast<__half2*>(Ol + (size_t)r * NH + cn) = tl;
                    } else {
                        *reinterpret_cast<__half2*>(Oh2 + (size_t)r * NH + cn - NH) = th;
                        *reinterpret_cast<__half2*>(Ol2 + (size_t)r * NH + cn - NH) = tl;
                    }
                } else if (MODE == 1) {
                    v0 += aux[cn]; v1 += aux[cn + 1];
                    __half2 t; t.x = __float2half_rn(v0); t.y = __float2half_rn(v1);
                    *reinterpret_cast<__half2*>(Oh + (size_t)b * sC + (size_t)r * ldc + cn) = t;
                } else {
                    const float* le = aux + (size_t)b * (NS * NC);
                    float2 t;
                    t.x = v0 + le[cn];
                    t.y = v1 + le[cn + 1];
                    __stcs(reinterpret_cast<float2*>(Of + (size_t)b * sC + (size_t)r * ldc + cn), t);
                }
            }
        }
}

// ---------------- launch ----------------
extern "C" void kernel_launch(void* const* d_in, const int* in_sizes, int n_in,
                              void* d_out, int out_size) {
    const float* seq  = (const float*)d_in[0];
    const float* U    = (const float*)d_in[1];
    const float* W_w  = (const float*)d_in[2];
    const float* W_b  = (const float*)d_in[3];
    const float* Ws_w = (const float*)d_in[4];
    const float* Ws_b = (const float*)d_in[5];
    const float* We_w = (const float*)d_in[6];
    const float* We_b = (const float*)d_in[7];
    float* out = (float*)d_out;

    __half *seq_hi, *seq_lo, *Wc_hi, *Hs_hi, *Hs_lo, *He_hi, *He_lo, *Ur_hi, *M;
    float *bcat, *Le, *Wsp;
    cudaGetSymbolAddress((void**)&seq_hi, g_seq_hi);
    cudaGetSymbolAddress((void**)&seq_lo, g_seq_lo);
    cudaGetSymbolAddress((void**)&Wc_hi,  g_Wcat_hi);
    cudaGetSymbolAddress((void**)&bcat,   g_bcat);
    cudaGetSymbolAddress((void**)&Hs_hi,  g_Hs_hi);
    cudaGetSymbolAddress((void**)&Hs_lo,  g_Hs_lo);
    cudaGetSymbolAddress((void**)&He_hi,  g_He_hi);
    cudaGetSymbolAddress((void**)&He_lo,  g_He_lo);
    cudaGetSymbolAddress((void**)&Ur_hi,  g_Ur_hi);
    cudaGetSymbolAddress((void**)&M,      g_M);
    cudaGetSymbolAddress((void**)&Le,     g_Le);
    cudaGetSymbolAddress((void**)&Wsp,    g_Wsp);

    const int SMEM_PROJ = 2 * (2 * 16384 + 16384);          // P=2, TN=128, ST=2: 96 KB
    const int SMEM_BIG  = 3 * (16384 + 256 * 128);          // P=1, TN=256, ST=3: 144 KB
    cudaFuncSetAttribute(gemm_mma<2, 0, 128, 2>, cudaFuncAttributeMaxDynamicSharedMemorySize, SMEM_PROJ);
    cudaFuncSetAttribute(gemm_mma<1, 1, 256, 3>, cudaFuncAttributeMaxDynamicSharedMemorySize, SMEM_BIG);
    cudaFuncSetAttribute(gemm_mma<1, 2, 256, 3>, cudaFuncAttributeMaxDynamicSharedMemorySize, SMEM_BIG);

    // fused prep
    prep_kernel<<<BLK_SPLIT + BLK_U + BLK_WCAT + BLK_WSP, 256>>>(
        seq, U, W_w, Ws_w, We_w, Ws_b, We_b);

    // fused projections: [Hs | He] = (seq_hi+seq_lo) @ Wcat_hi^T + bcat  (M=4096, N=512, K=768)
    gemm_mma<2, 0, 128, 2><<<dim3(32, 4, 1), 256, SMEM_PROJ>>>(
        seq_hi, seq_lo, Wc_hi, 0L, 0L, ND,
        bcat, Hs_hi, Hs_lo, He_hi, He_lo, nullptr, NH, 0L);

    le_kernel<<<(NB * NS) / 8, 256>>>(W_w, W_b);

    // GEMM1: M[b, e, (c,h)] = He_hi_b @ Ur_hi^T + W_s -> fp16  (512 x 8192 x 256)
    gemm_mma<1, 1, 256, 3><<<dim3(4, 32, NB), 256, SMEM_BIG>>>(
        He_hi, nullptr, Ur_hi,
        (long)NS * NH, 0L, NH,
        Wsp, M, nullptr, nullptr, nullptr, nullptr, NC * NH, (long)NS * NC * NH);

    // GEMM2: out[b, s, (e,c)] = Hs_hi_b @ M_b^T + Le -> fp32   (512 x 16384 x 256)
    gemm_mma<1, 2, 256, 3><<<dim3(4, 64, NB), 256, SMEM_BIG>>>(
        Hs_hi, nullptr, M,
        (long)NS * NH, (long)NS * NC * NH, NH,
        Le, nullptr, nullptr, nullptr, nullptr, out, NS * NC, (long)NS * NS * NC);
}